// round 6
// baseline (speedup 1.0000x reference)
#include <cuda_runtime.h>
#include <cstdint>

#define INV_TAU (1.0f/512.0f)

// Scratch (no cudaMalloc allowed)
__device__ float g_K[8ul*1024*1024];
__device__ float g_Q[8ul*1024*1024];
__device__ float g_O[8ul*1024*1024];
__device__ float g_Z[128ul*1024];

__device__ __forceinline__ unsigned f2t(float f) {
  unsigned u; asm("cvt.rna.tf32.f32 %0, %1;" : "=r"(u) : "f"(f)); return u;
}

__device__ __forceinline__ void mma8(float* c, unsigned a0, unsigned a1,
                                     unsigned a2, unsigned a3,
                                     unsigned b0, unsigned b1) {
  asm("mma.sync.aligned.m16n8k8.row.col.f32.tf32.tf32.f32 "
      "{%0,%1,%2,%3}, {%4,%5,%6,%7}, {%8,%9}, {%0,%1,%2,%3};"
      : "+f"(c[0]), "+f"(c[1]), "+f"(c[2]), "+f"(c[3])
      : "r"(a0), "r"(a1), "r"(a2), "r"(a3), "r"(b0), "r"(b1));
}

// Fragment-major layouts:
// A (row r = M-dim, col k):
//   word = (((r>>4)*KB8 + (k>>3))*32 + (r&7)*4 + (k&3))*4 + ((r>>3)&1) + 2*((k>>2)&1)
//   warp load: LDS.128 at (((mblk)*KB8+kb8)*128 + gi*16 + tj*4) -> {a0,a1,a2,a3}
// B (col n = N-dim, row k), row stride BSTR (=KB8*8+8, ≡8 mod 32):
//   word = n*BSTR + (k>>3)*8 + (k&3)*2 + ((k>>2)&1)
//   warp load: LDS.64 at (n*BSTR + kb8*8 + tj*2) -> {b0,b1}

// ---------------------------------------------------------------------------
// proj: C[b] = W (1024x1024 row-major) @ X[b] + bias
// Tile 128x128, k-step 32 (KB8=4, BSTR=40). 8 warps 2x4, warp tile 64x32.
// ---------------------------------------------------------------------------
__global__ __launch_bounds__(256) void proj_mma(
    const float* __restrict__ W, const float* __restrict__ X,
    const float* __restrict__ bias, float* __restrict__ C) {
  __shared__ __align__(16) unsigned As[4096];   // 8 mblk * 4 kb8 * 128
  __shared__ __align__(16) unsigned Bs[5120];   // 128 * 40
  const int b = blockIdx.z;
  const float* Xb = X + (size_t)b*1024*1024;
  float* Cb = C + (size_t)b*1024*1024;
  const int row0 = blockIdx.y*128, col0 = blockIdx.x*128;
  const int tid = threadIdx.x, wid = tid>>5, lane = tid&31;
  const int gi = lane>>2, tj = lane&3;
  const int wm = (wid>>2)*64, wn = (wid&3)*32;

  float acc[4][4][4] = {};

  for (int k0 = 0; k0 < 1024; k0 += 32) {
#pragma unroll
    for (int i = 0; i < 4; i++) {
      int idx = tid + i*256;
      int r = idx>>3, k4 = (idx&7)*4;     // r:0..127, k4:0,4,..,28
      float4 v = *(const float4*)&W[(size_t)(row0+r)*1024 + k0 + k4];
      int ab = (((r>>4)*4 + (k4>>3))*128) + (r&7)*16 + ((r>>3)&1) + (((k4>>2)&1)<<1);
      As[ab]    = f2t(v.x);
      As[ab+4]  = f2t(v.y);
      As[ab+8]  = f2t(v.z);
      As[ab+12] = f2t(v.w);
    }
#pragma unroll
    for (int i = 0; i < 4; i++) {
      int idx = tid + i*256;
      int kk = idx>>5, n4 = (idx&31)*4;   // kk:0..31, n4:0,4,..,124
      float4 v = *(const float4*)&Xb[(size_t)(k0+kk)*1024 + col0 + n4];
      int bb_ = n4*40 + (kk>>3)*8 + (kk&3)*2 + ((kk>>2)&1);
      Bs[bb_]     = f2t(v.x);
      Bs[bb_+40]  = f2t(v.y);
      Bs[bb_+80]  = f2t(v.z);
      Bs[bb_+120] = f2t(v.w);
    }
    __syncthreads();
#pragma unroll
    for (int c = 0; c < 4; c++) {
      uint4 a[4]; uint2 bb[4];
#pragma unroll
      for (int mt = 0; mt < 4; mt++)
        a[mt] = *(const uint4*)&As[(((wm>>4)+mt)*4 + c)*128 + gi*16 + tj*4];
#pragma unroll
      for (int nt = 0; nt < 4; nt++)
        bb[nt] = *(const uint2*)&Bs[(wn+nt*8+gi)*40 + c*8 + tj*2];
#pragma unroll
      for (int mt = 0; mt < 4; mt++)
#pragma unroll
        for (int nt = 0; nt < 4; nt++)
          mma8(acc[mt][nt], a[mt].x, a[mt].y, a[mt].z, a[mt].w,
               bb[nt].x, bb[nt].y);
    }
    __syncthreads();
  }
#pragma unroll
  for (int mt = 0; mt < 4; mt++) {
    int r0 = row0 + wm + mt*16 + gi;
    float bv0 = bias[r0], bv1 = bias[r0+8];
#pragma unroll
    for (int nt = 0; nt < 4; nt++) {
      int cc = col0 + wn + nt*8 + 2*tj;
      *(float2*)&Cb[(size_t)r0*1024 + cc] =
          make_float2(acc[mt][nt][0]+bv0, acc[mt][nt][1]+bv0);
      *(float2*)&Cb[(size_t)(r0+8)*1024 + cc] =
          make_float2(acc[mt][nt][2]+bv1, acc[mt][nt][3]+bv1);
    }
  }
}

// ---------------------------------------------------------------------------
// zpass: Z[l] = sum_m exp(S[l,m]/tau), S = K^T Q (contraction over d=64).
// Block: (bh, 128-l tile); m in 128 chunks. KB8=8, BSTR=72.
// ---------------------------------------------------------------------------
__global__ __launch_bounds__(256) void zpass_mma(
    const float* __restrict__ Kbuf, const float* __restrict__ Qbuf,
    float* __restrict__ Zbuf) {
  extern __shared__ __align__(16) unsigned zsm[];
  unsigned* Ks = zsm;                       // 8 mblk * 8 kb8 * 128 = 8192
  unsigned* Qs = zsm + 8192;                // 128 * 72 = 9216
  float* Zpart = (float*)(zsm + 17408);     // 4*128
  const int bh = blockIdx.y, l0 = blockIdx.x*128;
  const size_t base = ((size_t)(bh>>4)*1024 + (size_t)(bh&15)*64)*1024;
  const float* Kh = Kbuf + base;
  const float* Qh = Qbuf + base;
  const int tid = threadIdx.x, wid = tid>>5, lane = tid&31;
  const int gi = lane>>2, tj = lane&3;
  const int wl = (wid>>2)*64, wnn = (wid&3)*32;

  // K tile: element (d=r, l=c4+j) -> A(row l, col d)
#pragma unroll
  for (int i = 0; i < 8; i++) {
    int idx = tid + i*256;
    int r = idx>>5, c4 = (idx&31)*4;      // r:d 0..63, c4:l
    float4 v = *(const float4*)&Kh[(size_t)r*1024 + l0 + c4];
    int ab = (((c4>>4)*8 + (r>>3))*32 + (c4&7)*4 + (r&3))*4
             + ((c4>>3)&1) + (((r>>2)&1)<<1);
    Ks[ab]    = f2t(v.x);
    Ks[ab+16] = f2t(v.y);
    Ks[ab+32] = f2t(v.z);
    Ks[ab+48] = f2t(v.w);
  }
  float rs[8] = {};

  for (int m0 = 0; m0 < 1024; m0 += 128) {
    __syncthreads();
#pragma unroll
    for (int i = 0; i < 8; i++) {
      int idx = tid + i*256;
      int r = idx>>5, c4 = (idx&31)*4;    // r:d, c4:m
      float4 v = *(const float4*)&Qh[(size_t)r*1024 + m0 + c4];
      int bb_ = c4*72 + (r>>3)*8 + (r&3)*2 + ((r>>2)&1);
      Qs[bb_]     = f2t(v.x);
      Qs[bb_+72]  = f2t(v.y);
      Qs[bb_+144] = f2t(v.z);
      Qs[bb_+216] = f2t(v.w);
    }
    __syncthreads();
    float S[4][4][4] = {};
#pragma unroll
    for (int c = 0; c < 8; c++) {
      uint4 a[4]; uint2 bb[4];
#pragma unroll
      for (int mt = 0; mt < 4; mt++)
        a[mt] = *(const uint4*)&Ks[(((wl>>4)+mt)*8 + c)*128 + gi*16 + tj*4];
#pragma unroll
      for (int nt = 0; nt < 4; nt++)
        bb[nt] = *(const uint2*)&Qs[(wnn+nt*8+gi)*72 + c*8 + tj*2];
#pragma unroll
      for (int mt = 0; mt < 4; mt++)
#pragma unroll
        for (int nt = 0; nt < 4; nt++)
          mma8(S[mt][nt], a[mt].x, a[mt].y, a[mt].z, a[mt].w,
               bb[nt].x, bb[nt].y);
    }
#pragma unroll
    for (int mt = 0; mt < 4; mt++)
#pragma unroll
      for (int nt = 0; nt < 4; nt++) {
        rs[2*mt]   += __expf(S[mt][nt][0]*INV_TAU) + __expf(S[mt][nt][1]*INV_TAU);
        rs[2*mt+1] += __expf(S[mt][nt][2]*INV_TAU) + __expf(S[mt][nt][3]*INV_TAU);
      }
  }
#pragma unroll
  for (int i = 0; i < 8; i++) {
    rs[i] += __shfl_xor_sync(0xffffffffu, rs[i], 1);
    rs[i] += __shfl_xor_sync(0xffffffffu, rs[i], 2);
  }
  if (tj == 0) {
#pragma unroll
    for (int mt = 0; mt < 4; mt++) {
      Zpart[(wid&3)*128 + wl + mt*16 + gi]     = rs[2*mt];
      Zpart[(wid&3)*128 + wl + mt*16 + 8 + gi] = rs[2*mt+1];
    }
  }
  __syncthreads();
  if (tid < 128) {
    float z = Zpart[tid] + Zpart[128+tid] + Zpart[256+tid] + Zpart[384+tid];
    Zbuf[(size_t)bh*1024 + l0 + tid] = z;
  }
}

// ---------------------------------------------------------------------------
// opass: O[d,m] = sum_l (x[d,l]/Z[l]) * exp(S[l,m]/tau), flash-style.
// Block: (bh, 128-m tile); l in 64 chunks. KB8=8, BSTR=72.
// ---------------------------------------------------------------------------
__global__ __launch_bounds__(256) void opass_mma(
    const float* __restrict__ x, const float* __restrict__ Kbuf,
    const float* __restrict__ Qbuf, const float* __restrict__ Zbuf,
    float* __restrict__ Obuf) {
  extern __shared__ __align__(16) unsigned osm[];
  unsigned* Qs  = osm;                     // B-frag GEMM1: 128*72 = 9216
  unsigned* Ksc = osm + 9216;              // A-frag GEMM1: 4*8*128 = 4096
  unsigned* Xs  = osm + 13312;             // A-frag GEMM2: 4*8*128 = 4096
  unsigned* Ps  = osm + 17408;             // B-frag GEMM2: 128*72 = 9216
  float* Zr = (float*)(osm + 26624);       // 1024
  const int bh = blockIdx.y, m0 = blockIdx.x*128;
  const size_t base = ((size_t)(bh>>4)*1024 + (size_t)(bh&15)*64)*1024;
  const float* Kh = Kbuf + base;
  const float* Qh = Qbuf + base;
  const float* Xh = x + base;
  const int tid = threadIdx.x, wid = tid>>5, lane = tid&31;
  const int gi = lane>>2, tj = lane&3;
  const int wr = (wid>>2)*32;
  const int wn = (wid&3)*32;

#pragma unroll
  for (int i = 0; i < 8; i++) {
    int idx = tid + i*256;
    int r = idx>>5, c4 = (idx&31)*4;      // r:d, c4:m
    float4 v = *(const float4*)&Qh[(size_t)r*1024 + m0 + c4];
    int bb_ = c4*72 + (r>>3)*8 + (r&3)*2 + ((r>>2)&1);
    Qs[bb_]     = f2t(v.x);
    Qs[bb_+72]  = f2t(v.y);
    Qs[bb_+144] = f2t(v.z);
    Qs[bb_+216] = f2t(v.w);
  }
  {
    float4 z = *(const float4*)&Zbuf[(size_t)bh*1024 + tid*4];
    Zr[tid*4+0] = __frcp_rn(z.x);
    Zr[tid*4+1] = __frcp_rn(z.y);
    Zr[tid*4+2] = __frcp_rn(z.z);
    Zr[tid*4+3] = __frcp_rn(z.w);
  }

  float O[2][4][4] = {};

  for (int l0 = 0; l0 < 1024; l0 += 64) {
    __syncthreads();
#pragma unroll
    for (int i = 0; i < 4; i++) {
      int idx = tid + i*256;
      int r = idx>>4, c4 = (idx&15)*4;    // r:d 0..63, c4:l-offset 0..60
      float4 kv = *(const float4*)&Kh[(size_t)r*1024 + l0 + c4];
      // Ksc: A(row l, col d)
      int ka = (((c4>>4)*8 + (r>>3))*32 + (c4&7)*4 + (r&3))*4
               + ((c4>>3)&1) + (((r>>2)&1)<<1);
      Ksc[ka]    = f2t(kv.x);
      Ksc[ka+16] = f2t(kv.y);
      Ksc[ka+32] = f2t(kv.z);
      Ksc[ka+48] = f2t(kv.w);
      float4 xv = *(const float4*)&Xh[(size_t)r*1024 + l0 + c4];
      xv.x *= Zr[l0+c4+0]; xv.y *= Zr[l0+c4+1];
      xv.z *= Zr[l0+c4+2]; xv.w *= Zr[l0+c4+3];
      // Xs: A(row d, col l)
      int xa = (((r>>4)*8 + (c4>>3))*32 + (r&7)*4)*4
               + ((r>>3)&1) + (((c4>>2)&1)<<1);
      Xs[xa]    = f2t(xv.x);
      Xs[xa+4]  = f2t(xv.y);
      Xs[xa+8]  = f2t(xv.z);
      Xs[xa+12] = f2t(xv.w);
    }
    __syncthreads();
    // GEMM1: S chunk = K^T(64l x 64d) @ Q(64d x 128m)
    float S[2][4][4] = {};
#pragma unroll
    for (int c = 0; c < 8; c++) {
      uint4 a[2]; uint2 bb[4];
#pragma unroll
      for (int mt = 0; mt < 2; mt++)
        a[mt] = *(const uint4*)&Ksc[(((wr>>4)+mt)*8 + c)*128 + gi*16 + tj*4];
#pragma unroll
      for (int nt = 0; nt < 4; nt++)
        bb[nt] = *(const uint2*)&Qs[(wn+nt*8+gi)*72 + c*8 + tj*2];
#pragma unroll
      for (int mt = 0; mt < 2; mt++)
#pragma unroll
        for (int nt = 0; nt < 4; nt++)
          mma8(S[mt][nt], a[mt].x, a[mt].y, a[mt].z, a[mt].w,
               bb[nt].x, bb[nt].y);
    }
    // exp -> Ps (B-frag layout: word = m*72 + (l>>3)*8 + (l&3)*2 + ((l>>2)&1))
#pragma unroll
    for (int mt = 0; mt < 2; mt++) {
      int pb0 = ((wr>>3) + mt*2)*8 + (gi&3)*2 + ((gi>>2)&1);
#pragma unroll
      for (int nt = 0; nt < 4; nt++) {
        int m = wn + nt*8 + 2*tj;
        int pb = m*72 + pb0;
        Ps[pb]      = f2t(__expf(S[mt][nt][0]*INV_TAU));
        Ps[pb+72]   = f2t(__expf(S[mt][nt][1]*INV_TAU));
        Ps[pb+8]    = f2t(__expf(S[mt][nt][2]*INV_TAU));
        Ps[pb+80]   = f2t(__expf(S[mt][nt][3]*INV_TAU));
      }
    }
    __syncthreads();
    // GEMM2: O += X'(64d x 64l) @ P(64l x 128m)
#pragma unroll
    for (int c = 0; c < 8; c++) {
      uint4 a[2]; uint2 bb[4];
#pragma unroll
      for (int mt = 0; mt < 2; mt++)
        a[mt] = *(const uint4*)&Xs[(((wr>>4)+mt)*8 + c)*128 + gi*16 + tj*4];
#pragma unroll
      for (int nt = 0; nt < 4; nt++)
        bb[nt] = *(const uint2*)&Ps[(wn+nt*8+gi)*72 + c*8 + tj*2];
#pragma unroll
      for (int mt = 0; mt < 2; mt++)
#pragma unroll
        for (int nt = 0; nt < 4; nt++)
          mma8(O[mt][nt], a[mt].x, a[mt].y, a[mt].z, a[mt].w,
               bb[nt].x, bb[nt].y);
    }
  }
#pragma unroll
  for (int mt = 0; mt < 2; mt++) {
    int d = wr + mt*16 + gi;
#pragma unroll
    for (int nt = 0; nt < 4; nt++) {
      int c = m0 + wn + nt*8 + 2*tj;
      *(float2*)&Obuf[base + (size_t)d*1024 + c] =
          make_float2(O[mt][nt][0], O[mt][nt][1]);
      *(float2*)&Obuf[base + (size_t)(d+8)*1024 + c] =
          make_float2(O[mt][nt][2], O[mt][nt][3]);
    }
  }
}

// ---------------------------------------------------------------------------
extern "C" void kernel_launch(void* const* d_in, const int* in_sizes, int n_in,
                              void* d_out, int out_size) {
  (void)in_sizes; (void)n_in; (void)out_size;
  const float* x  = (const float*)d_in[0];
  const float* y  = (const float*)d_in[1];
  const float* Wk = (const float*)d_in[2];
  const float* bk = (const float*)d_in[3];
  const float* Wq = (const float*)d_in[4];
  const float* bq = (const float*)d_in[5];
  const float* Wp = (const float*)d_in[6];
  const float* bp = (const float*)d_in[7];
  float* out = (float*)d_out;

  float *Kp, *Qp, *Op, *Zp;
  cudaGetSymbolAddress((void**)&Kp, g_K);
  cudaGetSymbolAddress((void**)&Qp, g_Q);
  cudaGetSymbolAddress((void**)&Op, g_O);
  cudaGetSymbolAddress((void**)&Zp, g_Z);

  const int zsmem = (8192 + 9216 + 512) * 4;                    // 71,680 B
  const int osmem = (9216 + 4096 + 4096 + 9216 + 1024) * 4;     // 110,592 B
  cudaFuncSetAttribute(zpass_mma, cudaFuncAttributeMaxDynamicSharedMemorySize, zsmem);
  cudaFuncSetAttribute(opass_mma, cudaFuncAttributeMaxDynamicSharedMemorySize, osmem);

  dim3 pg(8, 8, 8);
  proj_mma<<<pg, 256>>>(Wk, x, bk, Kp);
  proj_mma<<<pg, 256>>>(Wq, y, bq, Qp);
  zpass_mma<<<dim3(8, 128), 256, zsmem>>>(Kp, Qp, Zp);
  opass_mma<<<dim3(8, 128), 256, osmem>>>(x, Kp, Qp, Zp, Op);
  proj_mma<<<pg, 256>>>(Wp, Op, bp, out);
}

// round 7
// speedup vs baseline: 2.6752x; 2.6752x over previous
#include <cuda_runtime.h>

#define INV_TAU (1.0f/512.0f)

// Scratch (no cudaMalloc allowed)
__device__ float g_K[8ul*1024*1024];
__device__ float g_Q[8ul*1024*1024];
__device__ float g_O[8ul*1024*1024];
__device__ float g_Z[128ul*1024];

__device__ __forceinline__ unsigned f2t(float f) {
  unsigned u; asm("cvt.rna.tf32.f32 %0, %1;" : "=r"(u) : "f"(f)); return u;
}

__device__ __forceinline__ void mma8(float* c, unsigned a0, unsigned a1,
                                     unsigned a2, unsigned a3,
                                     unsigned b0, unsigned b1) {
  asm("mma.sync.aligned.m16n8k8.row.col.f32.tf32.tf32.f32 "
      "{%0,%1,%2,%3}, {%4,%5,%6,%7}, {%8,%9}, {%0,%1,%2,%3};"
      : "+f"(c[0]), "+f"(c[1]), "+f"(c[2]), "+f"(c[3])
      : "r"(a0), "r"(a1), "r"(a2), "r"(a3), "r"(b0), "r"(b1));
}

// ---------------------------------------------------------------------------
// proj: C[b] = W (1024x1024 row-major) @ X[b] + bias
// Block tile 128x128, k-step 32. 8 warps 2x4; warp tile 64x32.
// B (X) tile register-prefetched one k-step ahead.
// ---------------------------------------------------------------------------
__global__ __launch_bounds__(256, 2) void proj_mma(
    const float* __restrict__ W, const float* __restrict__ X,
    const float* __restrict__ bias, float* __restrict__ C) {
  __shared__ unsigned As[128*36];
  __shared__ unsigned Bs[32*136];
  const int b = blockIdx.z;
  const float* Xb = X + (size_t)b*1024*1024;
  float* Cb = C + (size_t)b*1024*1024;
  const int row0 = blockIdx.y*128, col0 = blockIdx.x*128;
  const int tid = threadIdx.x, wid = tid>>5, lane = tid&31;
  const int gi = lane>>2, tj = lane&3;
  const int wm = (wid>>2)*64, wn = (wid&3)*32;

  float acc[4][4][4] = {};
  float4 pb[4];

  // prologue: prefetch B tile for k0 = 0
#pragma unroll
  for (int i = 0; i < 4; i++) {
    int idx = tid + i*256;
    int kk = idx>>5, n4 = (idx&31)*4;
    pb[i] = *(const float4*)&Xb[(size_t)kk*1024 + col0 + n4];
  }

  for (int k0 = 0; k0 < 1024; k0 += 32) {
#pragma unroll
    for (int i = 0; i < 4; i++) {
      int idx = tid + i*256;
      int r = idx>>3, k4 = (idx&7)*4;
      float4 v = *(const float4*)&W[(size_t)(row0+r)*1024 + k0 + k4];
      unsigned* p = &As[r*36 + k4];
      p[0]=f2t(v.x); p[1]=f2t(v.y); p[2]=f2t(v.z); p[3]=f2t(v.w);
    }
#pragma unroll
    for (int i = 0; i < 4; i++) {
      int idx = tid + i*256;
      int kk = idx>>5, n4 = (idx&31)*4;
      unsigned* p = &Bs[kk*136 + n4];
      p[0]=f2t(pb[i].x); p[1]=f2t(pb[i].y); p[2]=f2t(pb[i].z); p[3]=f2t(pb[i].w);
    }
    __syncthreads();
    if (k0 < 992) {
#pragma unroll
      for (int i = 0; i < 4; i++) {
        int idx = tid + i*256;
        int kk = idx>>5, n4 = (idx&31)*4;
        pb[i] = *(const float4*)&Xb[(size_t)(k0+32+kk)*1024 + col0 + n4];
      }
    }
#pragma unroll
    for (int c = 0; c < 4; c++) {
      const int kb = c*8;
      unsigned a[4][4], bb[4][2];
#pragma unroll
      for (int mt = 0; mt < 4; mt++) {
        int m = wm + mt*16;
        a[mt][0] = As[(m+gi)*36 + kb + tj];
        a[mt][1] = As[(m+8+gi)*36 + kb + tj];
        a[mt][2] = As[(m+gi)*36 + kb+4 + tj];
        a[mt][3] = As[(m+8+gi)*36 + kb+4 + tj];
      }
#pragma unroll
      for (int nt = 0; nt < 4; nt++) {
        int n = wn + nt*8 + gi;
        bb[nt][0] = Bs[(kb+tj)*136 + n];
        bb[nt][1] = Bs[(kb+4+tj)*136 + n];
      }
#pragma unroll
      for (int mt = 0; mt < 4; mt++)
#pragma unroll
        for (int nt = 0; nt < 4; nt++)
          mma8(acc[mt][nt], a[mt][0],a[mt][1],a[mt][2],a[mt][3],
               bb[nt][0], bb[nt][1]);
    }
    __syncthreads();
  }
#pragma unroll
  for (int mt = 0; mt < 4; mt++) {
    int r0 = row0 + wm + mt*16 + gi;
    float bv0 = bias[r0], bv1 = bias[r0+8];
#pragma unroll
    for (int nt = 0; nt < 4; nt++) {
      int cc = col0 + wn + nt*8 + 2*tj;
      *(float2*)&Cb[(size_t)r0*1024 + cc] =
          make_float2(acc[mt][nt][0]+bv0, acc[mt][nt][1]+bv0);
      *(float2*)&Cb[(size_t)(r0+8)*1024 + cc] =
          make_float2(acc[mt][nt][2]+bv1, acc[mt][nt][3]+bv1);
    }
  }
}

// ---------------------------------------------------------------------------
// zpass: Z[l] = sum_m exp(S[l,m]/tau), S = K^T Q (contraction over d=64).
// Block: (bh, 128-l tile); m in 128 chunks. Half of next Q tile prefetched.
// ---------------------------------------------------------------------------
__global__ __launch_bounds__(256, 2) void zpass_mma(
    const float* __restrict__ Kbuf, const float* __restrict__ Qbuf,
    float* __restrict__ Zbuf) {
  extern __shared__ unsigned zsm[];
  unsigned* Ks = zsm;                       // 64*136
  unsigned* Qs = zsm + 64*136;              // 64*136
  float* Zpart = (float*)(zsm + 2*64*136);  // 4*128
  const int bh = blockIdx.y, l0 = blockIdx.x*128;
  const size_t base = ((size_t)(bh>>4)*1024 + (size_t)(bh&15)*64)*1024;
  const float* Kh = Kbuf + base;
  const float* Qh = Qbuf + base;
  const int tid = threadIdx.x, wid = tid>>5, lane = tid&31;
  const int gi = lane>>2, tj = lane&3;
  const int wl = (wid>>2)*64, wnn = (wid&3)*32;

#pragma unroll
  for (int i = 0; i < 8; i++) {
    int idx = tid + i*256;
    int r = idx>>5, c4 = (idx&31)*4;
    float4 v = *(const float4*)&Kh[(size_t)r*1024 + l0 + c4];
    unsigned* p = &Ks[r*136 + c4];
    p[0]=f2t(v.x); p[1]=f2t(v.y); p[2]=f2t(v.z); p[3]=f2t(v.w);
  }
  float rs[8] = {};
  float4 pq[4];
#pragma unroll
  for (int i = 0; i < 4; i++) {
    int idx = tid + i*256;
    int r = idx>>5, c4 = (idx&31)*4;
    pq[i] = *(const float4*)&Qh[(size_t)r*1024 + c4];
  }

  for (int m0 = 0; m0 < 1024; m0 += 128) {
    __syncthreads();
#pragma unroll
    for (int i = 0; i < 4; i++) {
      int idx = tid + i*256;
      int r = idx>>5, c4 = (idx&31)*4;
      unsigned* p = &Qs[r*136 + c4];
      p[0]=f2t(pq[i].x); p[1]=f2t(pq[i].y); p[2]=f2t(pq[i].z); p[3]=f2t(pq[i].w);
    }
#pragma unroll
    for (int i = 4; i < 8; i++) {
      int idx = tid + i*256;
      int r = idx>>5, c4 = (idx&31)*4;
      float4 v = *(const float4*)&Qh[(size_t)r*1024 + m0 + c4];
      unsigned* p = &Qs[r*136 + c4];
      p[0]=f2t(v.x); p[1]=f2t(v.y); p[2]=f2t(v.z); p[3]=f2t(v.w);
    }
    __syncthreads();
    if (m0 < 896) {
#pragma unroll
      for (int i = 0; i < 4; i++) {
        int idx = tid + i*256;
        int r = idx>>5, c4 = (idx&31)*4;
        pq[i] = *(const float4*)&Qh[(size_t)r*1024 + m0 + 128 + c4];
      }
    }
    float S[4][4][4] = {};
#pragma unroll
    for (int db = 0; db < 64; db += 8) {
      unsigned a[4][4], bb[4][2];
#pragma unroll
      for (int mt = 0; mt < 4; mt++) {
        int l = wl + mt*16;
        a[mt][0] = Ks[(db+tj)*136 + l + gi];
        a[mt][1] = Ks[(db+tj)*136 + l + 8 + gi];
        a[mt][2] = Ks[(db+4+tj)*136 + l + gi];
        a[mt][3] = Ks[(db+4+tj)*136 + l + 8 + gi];
      }
#pragma unroll
      for (int nt = 0; nt < 4; nt++) {
        int n = wnn + nt*8 + gi;
        bb[nt][0] = Qs[(db+tj)*136 + n];
        bb[nt][1] = Qs[(db+4+tj)*136 + n];
      }
#pragma unroll
      for (int mt = 0; mt < 4; mt++)
#pragma unroll
        for (int nt = 0; nt < 4; nt++)
          mma8(S[mt][nt], a[mt][0],a[mt][1],a[mt][2],a[mt][3],
               bb[nt][0], bb[nt][1]);
    }
#pragma unroll
    for (int mt = 0; mt < 4; mt++)
#pragma unroll
      for (int nt = 0; nt < 4; nt++) {
        rs[2*mt]   += __expf(S[mt][nt][0]*INV_TAU) + __expf(S[mt][nt][1]*INV_TAU);
        rs[2*mt+1] += __expf(S[mt][nt][2]*INV_TAU) + __expf(S[mt][nt][3]*INV_TAU);
      }
  }
#pragma unroll
  for (int i = 0; i < 8; i++) {
    rs[i] += __shfl_xor_sync(0xffffffffu, rs[i], 1);
    rs[i] += __shfl_xor_sync(0xffffffffu, rs[i], 2);
  }
  if (tj == 0) {
#pragma unroll
    for (int mt = 0; mt < 4; mt++) {
      Zpart[(wid&3)*128 + wl + mt*16 + gi]     = rs[2*mt];
      Zpart[(wid&3)*128 + wl + mt*16 + 8 + gi] = rs[2*mt+1];
    }
  }
  __syncthreads();
  if (tid < 128) {
    float z = Zpart[tid] + Zpart[128+tid] + Zpart[256+tid] + Zpart[384+tid];
    Zbuf[(size_t)bh*1024 + l0 + tid] = z;
  }
}

// ---------------------------------------------------------------------------
// opass: O[d,m] = sum_l (x[d,l]/Z[l]) * exp(S[l,m]/tau), flash-style.
// Block: (bh, 128-m tile); l in 64 chunks. K tile register-prefetched.
// ---------------------------------------------------------------------------
__global__ __launch_bounds__(256, 2) void opass_mma(
    const float* __restrict__ x, const float* __restrict__ Kbuf,
    const float* __restrict__ Qbuf, const float* __restrict__ Zbuf,
    float* __restrict__ Obuf) {
  extern __shared__ unsigned osm[];
  unsigned* Qs  = osm;                         // 64*136 = 8704
  unsigned* Ksc = osm + 8704;                  // 64*72  = 4608
  unsigned* Xs  = osm + 8704 + 4608;           // 64*68  = 4352
  unsigned* Ps  = osm + 8704 + 4608 + 4352;    // 64*136 = 8704
  float* Zr = (float*)(osm + 8704 + 4608 + 4352 + 8704);  // 1024
  const int bh = blockIdx.y, m0 = blockIdx.x*128;
  const size_t base = ((size_t)(bh>>4)*1024 + (size_t)(bh&15)*64)*1024;
  const float* Kh = Kbuf + base;
  const float* Qh = Qbuf + base;
  const float* Xh = x + base;
  const int tid = threadIdx.x, wid = tid>>5, lane = tid&31;
  const int gi = lane>>2, tj = lane&3;
  const int wr = (wid>>2)*32;
  const int wn = (wid&3)*32;

#pragma unroll
  for (int i = 0; i < 8; i++) {
    int idx = tid + i*256;
    int r = idx>>5, c4 = (idx&31)*4;
    float4 v = *(const float4*)&Qh[(size_t)r*1024 + m0 + c4];
    unsigned* p = &Qs[r*136 + c4];
    p[0]=f2t(v.x); p[1]=f2t(v.y); p[2]=f2t(v.z); p[3]=f2t(v.w);
  }
  {
    float4 z = *(const float4*)&Zbuf[(size_t)bh*1024 + tid*4];
    Zr[tid*4+0] = __frcp_rn(z.x);
    Zr[tid*4+1] = __frcp_rn(z.y);
    Zr[tid*4+2] = __frcp_rn(z.z);
    Zr[tid*4+3] = __frcp_rn(z.w);
  }

  float O[2][4][4] = {};
  float4 pk[4];
#pragma unroll
  for (int i = 0; i < 4; i++) {
    int idx = tid + i*256;
    int r = idx>>4, c4 = (idx&15)*4;
    pk[i] = *(const float4*)&Kh[(size_t)r*1024 + c4];
  }

  for (int l0 = 0; l0 < 1024; l0 += 64) {
    __syncthreads();
#pragma unroll
    for (int i = 0; i < 4; i++) {
      int idx = tid + i*256;
      int r = idx>>4, c4 = (idx&15)*4;
      unsigned* p = &Ksc[r*72 + c4];
      p[0]=f2t(pk[i].x); p[1]=f2t(pk[i].y); p[2]=f2t(pk[i].z); p[3]=f2t(pk[i].w);
      float4 xv = *(const float4*)&Xh[(size_t)r*1024 + l0 + c4];
      xv.x *= Zr[l0+c4+0]; xv.y *= Zr[l0+c4+1];
      xv.z *= Zr[l0+c4+2]; xv.w *= Zr[l0+c4+3];
      unsigned* q = &Xs[r*68 + c4];
      q[0]=f2t(xv.x); q[1]=f2t(xv.y); q[2]=f2t(xv.z); q[3]=f2t(xv.w);
    }
    __syncthreads();
    if (l0 < 960) {
#pragma unroll
      for (int i = 0; i < 4; i++) {
        int idx = tid + i*256;
        int r = idx>>4, c4 = (idx&15)*4;
        pk[i] = *(const float4*)&Kh[(size_t)r*1024 + l0 + 64 + c4];
      }
    }
    // GEMM1: S chunk = K^T(64l x 64d) @ Q(64d x 128m)
    float S[2][4][4] = {};
#pragma unroll
    for (int db = 0; db < 64; db += 8) {
      unsigned a[2][4], bb[4][2];
#pragma unroll
      for (int mt = 0; mt < 2; mt++) {
        int l = wr + mt*16;
        a[mt][0] = Ksc[(db+tj)*72 + l + gi];
        a[mt][1] = Ksc[(db+tj)*72 + l + 8 + gi];
        a[mt][2] = Ksc[(db+4+tj)*72 + l + gi];
        a[mt][3] = Ksc[(db+4+tj)*72 + l + 8 + gi];
      }
#pragma unroll
      for (int nt = 0; nt < 4; nt++) {
        int n = wn + nt*8 + gi;
        bb[nt][0] = Qs[(db+tj)*136 + n];
        bb[nt][1] = Qs[(db+4+tj)*136 + n];
      }
#pragma unroll
      for (int mt = 0; mt < 2; mt++)
#pragma unroll
        for (int nt = 0; nt < 4; nt++)
          mma8(S[mt][nt], a[mt][0],a[mt][1],a[mt][2],a[mt][3],
               bb[nt][0], bb[nt][1]);
    }
    // exp -> Ps (tf32), paired uint2 stores
#pragma unroll
    for (int mt = 0; mt < 2; mt++) {
      int l = wr + mt*16 + gi;
#pragma unroll
      for (int nt = 0; nt < 4; nt++) {
        int m = wn + nt*8 + 2*tj;
        uint2 v0, v1;
        v0.x = f2t(__expf(S[mt][nt][0]*INV_TAU));
        v0.y = f2t(__expf(S[mt][nt][1]*INV_TAU));
        v1.x = f2t(__expf(S[mt][nt][2]*INV_TAU));
        v1.y = f2t(__expf(S[mt][nt][3]*INV_TAU));
        *(uint2*)&Ps[l*136 + m]     = v0;
        *(uint2*)&Ps[(l+8)*136 + m] = v1;
      }
    }
    __syncthreads();
    // GEMM2: O += X'(64d x 64l) @ P(64l x 128m)
#pragma unroll
    for (int lb = 0; lb < 64; lb += 8) {
      unsigned a[2][4], bb[4][2];
#pragma unroll
      for (int mt = 0; mt < 2; mt++) {
        int d = wr + mt*16;
        a[mt][0] = Xs[(d+gi)*68 + lb + tj];
        a[mt][1] = Xs[(d+8+gi)*68 + lb + tj];
        a[mt][2] = Xs[(d+gi)*68 + lb + 4 + tj];
        a[mt][3] = Xs[(d+8+gi)*68 + lb + 4 + tj];
      }
#pragma unroll
      for (int nt = 0; nt < 4; nt++) {
        int n = wn + nt*8 + gi;
        bb[nt][0] = Ps[(lb+tj)*136 + n];
        bb[nt][1] = Ps[(lb+4+tj)*136 + n];
      }
#pragma unroll
      for (int mt = 0; mt < 2; mt++)
#pragma unroll
        for (int nt = 0; nt < 4; nt++)
          mma8(O[mt][nt], a[mt][0],a[mt][1],a[mt][2],a[mt][3],
               bb[nt][0], bb[nt][1]);
    }
  }
#pragma unroll
  for (int mt = 0; mt < 2; mt++) {
    int d = wr + mt*16 + gi;
#pragma unroll
    for (int nt = 0; nt < 4; nt++) {
      int c = m0 + wn + nt*8 + 2*tj;
      *(float2*)&Obuf[base + (size_t)d*1024 + c] =
          make_float2(O[mt][nt][0], O[mt][nt][1]);
      *(float2*)&Obuf[base + (size_t)(d+8)*1024 + c] =
          make_float2(O[mt][nt][2], O[mt][nt][3]);
    }
  }
}

// ---------------------------------------------------------------------------
extern "C" void kernel_launch(void* const* d_in, const int* in_sizes, int n_in,
                              void* d_out, int out_size) {
  (void)in_sizes; (void)n_in; (void)out_size;
  const float* x  = (const float*)d_in[0];
  const float* y  = (const float*)d_in[1];
  const float* Wk = (const float*)d_in[2];
  const float* bk = (const float*)d_in[3];
  const float* Wq = (const float*)d_in[4];
  const float* bq = (const float*)d_in[5];
  const float* Wp = (const float*)d_in[6];
  const float* bp = (const float*)d_in[7];
  float* out = (float*)d_out;

  float *Kp, *Qp, *Op, *Zp;
  cudaGetSymbolAddress((void**)&Kp, g_K);
  cudaGetSymbolAddress((void**)&Qp, g_Q);
  cudaGetSymbolAddress((void**)&Op, g_O);
  cudaGetSymbolAddress((void**)&Zp, g_Z);

  const int zsmem = (2*64*136 + 4*128) * 4;                    // 71,680 B
  const int osmem = (8704 + 4608 + 4352 + 8704 + 1024) * 4;    // 109,568 B
  cudaFuncSetAttribute(zpass_mma, cudaFuncAttributeMaxDynamicSharedMemorySize, zsmem);
  cudaFuncSetAttribute(opass_mma, cudaFuncAttributeMaxDynamicSharedMemorySize, osmem);

  dim3 pg(8, 8, 8);
  proj_mma<<<pg, 256>>>(Wk, x, bk, Kp);
  proj_mma<<<pg, 256>>>(Wq, y, bq, Qp);
  zpass_mma<<<dim3(8, 128), 256, zsmem>>>(Kp, Qp, Zp);
  opass_mma<<<dim3(8, 128), 256, osmem>>>(x, Kp, Qp, Zp, Op);
  proj_mma<<<pg, 256>>>(Wp, Op, bp, out);
}

// round 10
// speedup vs baseline: 3.5866x; 1.3407x over previous
#include <cuda_runtime.h>
#include <cuda_fp16.h>

#define INV_TAU (1.0f/512.0f)

// Scratch (no cudaMalloc allowed)
__device__ __half g_Xt[8ul*1024*1024];     // x^T fp16 [b][l][s]
__device__ __half g_Yt[8ul*1024*1024];     // y^T fp16 [b][l][s]
__device__ __half g_Ot[8ul*1024*1024];     // O^T fp16 [b][m][s]
__device__ __half g_Kt[128ul*1024*64];     // K^T fp16 [bh][l][d]
__device__ __half g_Qt[128ul*1024*64];     // Q^T fp16 [bh][m][d]
__device__ float  g_Z[128ul*1024];

__device__ __forceinline__ unsigned f2h2(float a, float b) {
  __half2 h = __floats2half2_rn(a, b);
  return *(unsigned*)&h;
}

__device__ __forceinline__ void mma16(float* c, unsigned a0, unsigned a1,
                                      unsigned a2, unsigned a3,
                                      unsigned b0, unsigned b1) {
  asm("mma.sync.aligned.m16n8k16.row.col.f32.f16.f16.f32 "
      "{%0,%1,%2,%3}, {%4,%5,%6,%7}, {%8,%9}, {%0,%1,%2,%3};"
      : "+f"(c[0]), "+f"(c[1]), "+f"(c[2]), "+f"(c[3])
      : "r"(a0), "r"(a1), "r"(a2), "r"(a3), "r"(b0), "r"(b1));
}

// ---------------------------------------------------------------------------
// prep: transpose 1024x1024 fp32 -> fp16 per batch: out[l][s] = in[s][l]
// ---------------------------------------------------------------------------
__global__ __launch_bounds__(256, 2) void prep_t(
    const float* __restrict__ in, __half* __restrict__ out) {
  __shared__ float t[64][65];
  const int z = blockIdx.z;
  const int r0 = blockIdx.y * 64, c0 = blockIdx.x * 64;
  const int tid = threadIdx.x;
  const size_t base = (size_t)z * 1024 * 1024;
  const int tr = tid >> 4, tc4 = (tid & 15) * 4;
#pragma unroll
  for (int i = 0; i < 4; i++) {
    int row = tr + i * 16;
    float4 v = *(const float4*)&in[base + (size_t)(r0 + row) * 1024 + c0 + tc4];
    t[row][tc4+0] = v.x; t[row][tc4+1] = v.y;
    t[row][tc4+2] = v.z; t[row][tc4+3] = v.w;
  }
  __syncthreads();
#pragma unroll
  for (int i = 0; i < 4; i++) {
    int orow = tr + i * 16;
    uint2 u;
    u.x = f2h2(t[tc4+0][orow], t[tc4+1][orow]);
    u.y = f2h2(t[tc4+2][orow], t[tc4+3][orow]);
    *(uint2*)&out[base + (size_t)(c0 + orow) * 1024 + r0 + tc4] = u;
  }
}

// ---------------------------------------------------------------------------
// proj: C[b] = W (1024x1024 fp32 row-major) @ X[b] + bias, X given transposed
// fp16 (Xt[l][s]). Tile 128(m)x128(n), k-step 32. Warps 2x4, warp tile 64x32.
// fp32_out=1: write fp32 C[s][l] to Cout.  fp32_out=0: write fp16 transposed
// per-head Tout[bh][l][d] via smem-staged epilogue.
// ---------------------------------------------------------------------------
__global__ __launch_bounds__(256, 2) void proj_h(
    const float* __restrict__ W, const __half* __restrict__ Xt,
    const float* __restrict__ bias, float* __restrict__ Cout,
    __half* __restrict__ Tout, int fp32_out) {
  extern __shared__ __half psm[];
  __half* As = psm;            // 128*40 halves
  __half* Bs = psm + 5120;     // 128*40 halves
  unsigned* As2 = (unsigned*)As;
  unsigned* Bs2 = (unsigned*)Bs;
  const int b = blockIdx.z;
  const int row0 = blockIdx.y*128, col0 = blockIdx.x*128;
  const __half* Xb = Xt + (size_t)b*1024*1024;
  const int tid = threadIdx.x, wid = tid>>5, lane = tid&31;
  const int gi = lane>>2, tj = lane&3;
  const int wm = (wid>>2)*64, wn = (wid&3)*32;

  float acc[4][4][4] = {};
  uint4 pb0, pb1;
  {
    const __half* src = &Xb[(size_t)(col0 + (tid>>1))*1024 + (tid&1)*16];
    pb0 = *(const uint4*)src;
    pb1 = *(const uint4*)(src + 8);
  }

  for (int k0 = 0; k0 < 1024; k0 += 32) {
#pragma unroll
    for (int i = 0; i < 4; i++) {
      int idx = tid + i*256;
      int r = idx>>3, k4 = (idx&7)*4;
      float4 v = *(const float4*)&W[(size_t)(row0+r)*1024 + k0 + k4];
      *(uint2*)&As[r*40 + k4] = make_uint2(f2h2(v.x, v.y), f2h2(v.z, v.w));
    }
    {
      int n = tid>>1, sg = (tid&1)*16;
      *(uint4*)&Bs[n*40 + sg] = pb0;
      *(uint4*)&Bs[n*40 + sg + 8] = pb1;
    }
    __syncthreads();
    if (k0 < 992) {
      const __half* src = &Xb[(size_t)(col0 + (tid>>1))*1024 + k0 + 32 + (tid&1)*16];
      pb0 = *(const uint4*)src;
      pb1 = *(const uint4*)(src + 8);
    }
#pragma unroll
    for (int c = 0; c < 2; c++) {
      unsigned a[4][4], bb[4][2];
#pragma unroll
      for (int mt = 0; mt < 4; mt++) {
        int base = (wm + mt*16 + gi)*20 + c*8 + tj;
        a[mt][0] = As2[base];
        a[mt][1] = As2[base + 160];
        a[mt][2] = As2[base + 4];
        a[mt][3] = As2[base + 164];
      }
#pragma unroll
      for (int nt = 0; nt < 4; nt++) {
        int nb = (wn + nt*8 + gi)*20 + c*8 + tj;
        bb[nt][0] = Bs2[nb];
        bb[nt][1] = Bs2[nb + 4];
      }
#pragma unroll
      for (int mt = 0; mt < 4; mt++)
#pragma unroll
        for (int nt = 0; nt < 4; nt++)
          mma16(acc[mt][nt], a[mt][0],a[mt][1],a[mt][2],a[mt][3],
                bb[nt][0], bb[nt][1]);
    }
    __syncthreads();
  }

  if (fp32_out) {
    float* Cb = Cout + (size_t)b*1024*1024;
#pragma unroll
    for (int mt = 0; mt < 4; mt++) {
      int r0_ = row0 + wm + mt*16 + gi;
      float bv0 = bias[r0_], bv1 = bias[r0_+8];
#pragma unroll
      for (int nt = 0; nt < 4; nt++) {
        int cc = col0 + wn + nt*8 + 2*tj;
        *(float2*)&Cb[(size_t)r0_*1024 + cc] =
            make_float2(acc[mt][nt][0]+bv0, acc[mt][nt][1]+bv0);
        *(float2*)&Cb[(size_t)(r0_+8)*1024 + cc] =
            make_float2(acc[mt][nt][2]+bv1, acc[mt][nt][3]+bv1);
      }
    }
  } else {
    // stage transposed tile Cts[l 128][s 128] (stride 136) then coalesced write
    __half* Cts = psm;   // 128*136 = 17408 halves = 34816 B
    __syncthreads();
#pragma unroll
    for (int mt = 0; mt < 4; mt++) {
      int r_ = wm + mt*16 + gi;
      float bv0 = bias[row0 + r_], bv1 = bias[row0 + r_ + 8];
#pragma unroll
      for (int nt = 0; nt < 4; nt++) {
        int c_ = wn + nt*8 + 2*tj;
        Cts[c_*136 + r_]       = __float2half(acc[mt][nt][0] + bv0);
        Cts[(c_+1)*136 + r_]   = __float2half(acc[mt][nt][1] + bv0);
        Cts[c_*136 + r_+8]     = __float2half(acc[mt][nt][2] + bv1);
        Cts[(c_+1)*136 + r_+8] = __float2half(acc[mt][nt][3] + bv1);
      }
    }
    __syncthreads();
    int l = tid>>1, part = tid&1;
    size_t obase = ((size_t)(b*16 + (row0>>6) + part)*1024 + col0 + l)*64;
#pragma unroll
    for (int j = 0; j < 8; j++)
      *(uint4*)&Tout[obase + j*8] = *(const uint4*)&Cts[l*136 + part*64 + j*8];
  }
}

// ---------------------------------------------------------------------------
// zpass: Z[l] = sum_m exp(S[l,m]/tau).  Computes S^T[m][l] = Q^T K tiles.
// Block (bh, 128-l tile); loop m in 128 chunks. Warps: 2(m-half) x 4(l-32).
// ---------------------------------------------------------------------------
__global__ __launch_bounds__(256, 2) void zpass_h(
    const __half* __restrict__ Kt, const __half* __restrict__ Qt,
    float* __restrict__ Z) {
  extern __shared__ __half zsm[];
  __half* Ks = zsm;            // 128*72
  __half* Qs = zsm + 9216;     // 128*72
  float* Zp = (float*)(zsm + 18432);  // 256 floats
  unsigned* Ks2 = (unsigned*)Ks;
  unsigned* Qs2 = (unsigned*)Qs;
  const int bh = blockIdx.y, l0 = blockIdx.x*128;
  const __half* Kb = Kt + (size_t)bh*65536;
  const __half* Qb = Qt + (size_t)bh*65536;
  const int tid = threadIdx.x, wid = tid>>5, lane = tid&31;
  const int gi = lane>>2, tj = lane&3;
  const int wm_ = (wid>>2)*64, wl_ = (wid&3)*32;

  {
    int r = tid>>1, sg = (tid&1)*32;
    const uint4* s = (const uint4*)&Kb[(size_t)(l0 + r)*64 + sg];
    uint4* d = (uint4*)&Ks[r*72 + sg];
    d[0]=s[0]; d[1]=s[1]; d[2]=s[2]; d[3]=s[3];
  }
  float rs[4][2] = {};
  uint4 pq[4];
  {
    int r = tid>>1, sg = (tid&1)*32;
    const uint4* s = (const uint4*)&Qb[(size_t)r*64 + sg];
    pq[0]=s[0]; pq[1]=s[1]; pq[2]=s[2]; pq[3]=s[3];
  }

  for (int m0 = 0; m0 < 1024; m0 += 128) {
    __syncthreads();
    {
      int r = tid>>1, sg = (tid&1)*32;
      uint4* d = (uint4*)&Qs[r*72 + sg];
      d[0]=pq[0]; d[1]=pq[1]; d[2]=pq[2]; d[3]=pq[3];
    }
    __syncthreads();
    if (m0 < 896) {
      int r = tid>>1, sg = (tid&1)*32;
      const uint4* s = (const uint4*)&Qb[(size_t)(m0 + 128 + r)*64 + sg];
      pq[0]=s[0]; pq[1]=s[1]; pq[2]=s[2]; pq[3]=s[3];
    }
    float S[4][4][4] = {};
#pragma unroll
    for (int c = 0; c < 4; c++) {
      unsigned a[4][4], bb[4][2];
#pragma unroll
      for (int mt = 0; mt < 4; mt++) {
        int base = (wm_ + mt*16 + gi)*36 + c*8 + tj;
        a[mt][0] = Qs2[base];
        a[mt][1] = Qs2[base + 288];
        a[mt][2] = Qs2[base + 4];
        a[mt][3] = Qs2[base + 292];
      }
#pragma unroll
      for (int nt = 0; nt < 4; nt++) {
        int nb = (wl_ + nt*8 + gi)*36 + c*8 + tj;
        bb[nt][0] = Ks2[nb];
        bb[nt][1] = Ks2[nb + 4];
      }
#pragma unroll
      for (int mt = 0; mt < 4; mt++)
#pragma unroll
        for (int nt = 0; nt < 4; nt++)
          mma16(S[mt][nt], a[mt][0],a[mt][1],a[mt][2],a[mt][3],
                bb[nt][0], bb[nt][1]);
    }
#pragma unroll
    for (int mt = 0; mt < 4; mt++)
#pragma unroll
      for (int nt = 0; nt < 4; nt++) {
        rs[nt][0] += __expf(S[mt][nt][0]*INV_TAU) + __expf(S[mt][nt][2]*INV_TAU);
        rs[nt][1] += __expf(S[mt][nt][1]*INV_TAU) + __expf(S[mt][nt][3]*INV_TAU);
      }
  }
#pragma unroll
  for (int nt = 0; nt < 4; nt++)
#pragma unroll
    for (int j = 0; j < 2; j++) {
      float v = rs[nt][j];
      v += __shfl_xor_sync(0xffffffffu, v, 4);
      v += __shfl_xor_sync(0xffffffffu, v, 8);
      v += __shfl_xor_sync(0xffffffffu, v, 16);
      rs[nt][j] = v;
    }
  if (gi == 0) {
#pragma unroll
    for (int nt = 0; nt < 4; nt++)
#pragma unroll
      for (int j = 0; j < 2; j++)
        Zp[(wid>>2)*128 + wl_ + nt*8 + 2*tj + j] = rs[nt][j];
  }
  __syncthreads();
  if (tid < 128)
    Z[(size_t)bh*1024 + l0 + tid] = Zp[tid] + Zp[128 + tid];
}

// ---------------------------------------------------------------------------
// opass: O[d,m] = sum_l (x[d,l]/Z[l]) * exp(S[l,m]/tau).
// GEMM1 computes S^T[m][l] (A=Qt rows, B=Kt rows); P stored [m][l];
// GEMM2: O[d][m] = X'[d][l] @ P^T via B=[n=m][k=l]=Ps rows. Output Ot[m][s].
// ---------------------------------------------------------------------------
__global__ __launch_bounds__(256, 2) void opass_h(
    const float* __restrict__ x, const __half* __restrict__ Kt,
    const __half* __restrict__ Qt, const float* __restrict__ Z,
    __half* __restrict__ Ot) {
  extern __shared__ __half osm[];
  __half* Qs = osm;             // 128*72 = 9216 halves
  __half* Ks = osm + 9216;      // 64*72 = 4608
  __half* Xs = osm + 13824;     // 64*72 = 4608
  __half* Ps = osm + 18432;     // 128*72 = 9216
  float* Zr = (float*)(osm + 27648);  // 1024 floats
  unsigned* Qs2 = (unsigned*)Qs;
  unsigned* Ks2 = (unsigned*)Ks;
  unsigned* Xs2 = (unsigned*)Xs;
  unsigned* Ps2 = (unsigned*)Ps;
  const int bh = blockIdx.y, m0 = blockIdx.x*128;
  const int b = bh>>4, h = bh&15;
  const __half* Kb = Kt + (size_t)bh*65536;
  const __half* Qb = Qt + (size_t)bh*65536;
  const float* Xh = x + ((size_t)b*1024 + h*64)*1024;
  const int tid = threadIdx.x, wid = tid>>5, lane = tid&31;
  const int gi = lane>>2, tj = lane&3;
  const int wm1 = (wid>>2)*64, wl1 = (wid&3)*16;   // GEMM1 warp tile
  const int wr2 = (wid>>2)*32, wn2 = (wid&3)*32;   // GEMM2 warp tile

  {
    int r = tid>>1, sg = (tid&1)*32;
    const uint4* s = (const uint4*)&Qb[(size_t)(m0 + r)*64 + sg];
    uint4* d = (uint4*)&Qs[r*72 + sg];
    d[0]=s[0]; d[1]=s[1]; d[2]=s[2]; d[3]=s[3];
  }
  {
    float4 z = *(const float4*)&Z[(size_t)bh*1024 + tid*4];
    Zr[tid*4+0] = __frcp_rn(z.x);
    Zr[tid*4+1] = __frcp_rn(z.y);
    Zr[tid*4+2] = __frcp_rn(z.z);
    Zr[tid*4+3] = __frcp_rn(z.w);
  }
  __syncthreads();

  float O[2][4][4] = {};
  uint4 pk0, pk1;
  {
    int r = tid>>2, sg = (tid&3)*16;
    const uint4* s = (const uint4*)&Kb[(size_t)r*64 + sg];
    pk0 = s[0]; pk1 = s[1];
  }

  for (int l0 = 0; l0 < 1024; l0 += 64) {
    __syncthreads();
    {
      int r = tid>>2, sg = (tid&3)*16;
      uint4* d = (uint4*)&Ks[r*72 + sg];
      d[0] = pk0; d[1] = pk1;
    }
    {
      int r = tid>>2, c16 = (tid&3)*16;
#pragma unroll
      for (int j = 0; j < 4; j++) {
        int c4 = c16 + j*4;
        float4 v = *(const float4*)&Xh[(size_t)r*1024 + l0 + c4];
        v.x *= Zr[l0+c4+0]; v.y *= Zr[l0+c4+1];
        v.z *= Zr[l0+c4+2]; v.w *= Zr[l0+c4+3];
        *(uint2*)&Xs[r*72 + c4] = make_uint2(f2h2(v.x, v.y), f2h2(v.z, v.w));
      }
    }
    __syncthreads();
    if (l0 < 960) {
      int r = tid>>2, sg = (tid&3)*16;
      const uint4* s = (const uint4*)&Kb[(size_t)(l0 + 64 + r)*64 + sg];
      pk0 = s[0]; pk1 = s[1];
    }
    // GEMM1: S^T[m 128][l 64] = Q^T K
    float S[4][2][4] = {};
#pragma unroll
    for (int c = 0; c < 4; c++) {
      unsigned a[4][4], bb[2][2];
#pragma unroll
      for (int mt = 0; mt < 4; mt++) {
        int base = (wm1 + mt*16 + gi)*36 + c*8 + tj;
        a[mt][0] = Qs2[base];
        a[mt][1] = Qs2[base + 288];
        a[mt][2] = Qs2[base + 4];
        a[mt][3] = Qs2[base + 292];
      }
#pragma unroll
      for (int nt = 0; nt < 2; nt++) {
        int nb = (wl1 + nt*8 + gi)*36 + c*8 + tj;
        bb[nt][0] = Ks2[nb];
        bb[nt][1] = Ks2[nb + 4];
      }
#pragma unroll
      for (int mt = 0; mt < 4; mt++)
#pragma unroll
        for (int nt = 0; nt < 2; nt++)
          mma16(S[mt][nt], a[mt][0],a[mt][1],a[mt][2],a[mt][3],
                bb[nt][0], bb[nt][1]);
    }
    // exp -> Ps[m][l] (half2 vectorized)
#pragma unroll
    for (int mt = 0; mt < 4; mt++) {
      int m_ = wm1 + mt*16 + gi;
#pragma unroll
      for (int nt = 0; nt < 2; nt++) {
        int lu = wl1/2 + nt*4 + tj;   // uint index of l-pair
        Ps2[m_*36 + lu] =
            f2h2(__expf(S[mt][nt][0]*INV_TAU), __expf(S[mt][nt][1]*INV_TAU));
        Ps2[(m_+8)*36 + lu] =
            f2h2(__expf(S[mt][nt][2]*INV_TAU), __expf(S[mt][nt][3]*INV_TAU));
      }
    }
    __syncthreads();
    // GEMM2: O[d 64][m 128] += X'[d][l] @ P^T
#pragma unroll
    for (int c = 0; c < 4; c++) {
      unsigned a[2][4], bb[4][2];
#pragma unroll
      for (int mt = 0; mt < 2; mt++) {
        int base = (wr2 + mt*16 + gi)*36 + c*8 + tj;
        a[mt][0] = Xs2[base];
        a[mt][1] = Xs2[base + 288];
        a[mt][2] = Xs2[base + 4];
        a[mt][3] = Xs2[base + 292];
      }
#pragma unroll
      for (int nt = 0; nt < 4; nt++) {
        int nb = (wn2 + nt*8 + gi)*36 + c*8 + tj;
        bb[nt][0] = Ps2[nb];
        bb[nt][1] = Ps2[nb + 4];
      }
#pragma unroll
      for (int mt = 0; mt < 2; mt++)
#pragma unroll
        for (int nt = 0; nt < 4; nt++)
          mma16(O[mt][nt], a[mt][0],a[mt][1],a[mt][2],a[mt][3],
                bb[nt][0], bb[nt][1]);
    }
  }
  // Epilogue: stage Os[m 128][d 64] (stride 72) over Qs, then coalesced write
  __syncthreads();
  __half* Os = Qs;
#pragma unroll
  for (int mt = 0; mt < 2; mt++) {
    int d_ = wr2 + mt*16 + gi;
#pragma unroll
    for (int nt = 0; nt < 4; nt++) {
      int m_ = wn2 + nt*8 + 2*tj;
      Os[m_*72 + d_]       = __float2half(O[mt][nt][0]);
      Os[(m_+1)*72 + d_]   = __float2half(O[mt][nt][1]);
      Os[m_*72 + d_+8]     = __float2half(O[mt][nt][2]);
      Os[(m_+1)*72 + d_+8] = __float2half(O[mt][nt][3]);
    }
  }
  __syncthreads();
  {
    // FIX (R8 bug): copy the FULL 32-half span per thread (4 x uint4),
    // previously only 16 halves -> d in [16,32) and [48,64) were dropped.
    int m = tid>>1, sg = (tid&1)*32;
    const uint4* s = (const uint4*)&Os[m*72 + sg];
    uint4 v0 = s[0], v1 = s[1], v2 = s[2], v3 = s[3];
    __half* dst = &Ot[((size_t)b*1024 + m0 + m)*1024 + h*64 + sg];
    *(uint4*)dst        = v0;
    *(uint4*)(dst + 8)  = v1;
    *(uint4*)(dst + 16) = v2;
    *(uint4*)(dst + 24) = v3;
  }
}

// ---------------------------------------------------------------------------
extern "C" void kernel_launch(void* const* d_in, const int* in_sizes, int n_in,
                              void* d_out, int out_size) {
  (void)in_sizes; (void)n_in; (void)out_size;
  const float* x  = (const float*)d_in[0];
  const float* y  = (const float*)d_in[1];
  const float* Wk = (const float*)d_in[2];
  const float* bk = (const float*)d_in[3];
  const float* Wq = (const float*)d_in[4];
  const float* bq = (const float*)d_in[5];
  const float* Wp = (const float*)d_in[6];
  const float* bp = (const float*)d_in[7];
  float* out = (float*)d_out;

  __half *Xt, *Yt, *Otp, *Ktp, *Qtp; float* Zp;
  cudaGetSymbolAddress((void**)&Xt,  g_Xt);
  cudaGetSymbolAddress((void**)&Yt,  g_Yt);
  cudaGetSymbolAddress((void**)&Otp, g_Ot);
  cudaGetSymbolAddress((void**)&Ktp, g_Kt);
  cudaGetSymbolAddress((void**)&Qtp, g_Qt);
  cudaGetSymbolAddress((void**)&Zp,  g_Z);

  const int psmem = 128*136*2;                    // 34,816 B
  const int zsmem = 2*128*72*2 + 256*4;           // 37,888 B
  const int osmem = (9216+4608+4608+9216)*2 + 1024*4;  // 59,392 B
  cudaFuncSetAttribute(proj_h,  cudaFuncAttributeMaxDynamicSharedMemorySize, psmem);
  cudaFuncSetAttribute(zpass_h, cudaFuncAttributeMaxDynamicSharedMemorySize, zsmem);
  cudaFuncSetAttribute(opass_h, cudaFuncAttributeMaxDynamicSharedMemorySize, osmem);

  dim3 tg(16, 16, 8), pg(8, 8, 8);
  prep_t<<<tg, 256>>>(x, Xt);
  prep_t<<<tg, 256>>>(y, Yt);
  proj_h<<<pg, 256, psmem>>>(Wk, Xt, bk, nullptr, Ktp, 0);
  proj_h<<<pg, 256, psmem>>>(Wq, Yt, bq, nullptr, Qtp, 0);
  zpass_h<<<dim3(8, 128), 256, zsmem>>>(Ktp, Qtp, Zp);
  opass_h<<<dim3(8, 128), 256, osmem>>>(x, Ktp, Qtp, Zp, Otp);
  proj_h<<<pg, 256, psmem>>>(Wp, Otp, bp, out, nullptr, 1);
}

// round 11
// speedup vs baseline: 3.6845x; 1.0273x over previous
#include <cuda_runtime.h>
#include <cuda_fp16.h>

#define INV_TAU (1.0f/512.0f)

// Scratch (no cudaMalloc allowed)
__device__ __half g_Xt[8ul*1024*1024];     // x^T fp16 [b][l][s]
__device__ __half g_Yt[8ul*1024*1024];     // y^T fp16 [b][l][s]
__device__ __half g_Ot[8ul*1024*1024];     // O^T fp16 [b][m][s]
__device__ __half g_X16[8ul*1024*1024];    // x fp16 [b][s][l] (non-transposed)
__device__ __half g_Wh[3ul*1024*1024];     // Wk,Wq,Wp fp16 row-major
__device__ __half g_Kt[128ul*1024*64];     // K^T fp16 [bh][l][d]
__device__ __half g_Qt[128ul*1024*64];     // Q^T fp16 [bh][m][d]
__device__ float  g_Z[128ul*1024];

__device__ __forceinline__ unsigned f2h2(float a, float b) {
  __half2 h = __floats2half2_rn(a, b);
  return *(unsigned*)&h;
}

__device__ __forceinline__ void mma16(float* c, unsigned a0, unsigned a1,
                                      unsigned a2, unsigned a3,
                                      unsigned b0, unsigned b1) {
  asm("mma.sync.aligned.m16n8k16.row.col.f32.f16.f16.f32 "
      "{%0,%1,%2,%3}, {%4,%5,%6,%7}, {%8,%9}, {%0,%1,%2,%3};"
      : "+f"(c[0]), "+f"(c[1]), "+f"(c[2]), "+f"(c[3])
      : "r"(a0), "r"(a1), "r"(a2), "r"(a3), "r"(b0), "r"(b1));
}

// ---------------------------------------------------------------------------
// cvt16: elementwise fp32 -> fp16 (n = total elements, multiple of 1024)
// ---------------------------------------------------------------------------
__global__ __launch_bounds__(256) void cvt16(
    const float* __restrict__ in, __half* __restrict__ out) {
  size_t i = ((size_t)blockIdx.x*256 + threadIdx.x)*4;
  float4 v = *(const float4*)&in[i];
  *(uint2*)&out[i] = make_uint2(f2h2(v.x, v.y), f2h2(v.z, v.w));
}

// ---------------------------------------------------------------------------
// prep_t: transpose 1024x1024 fp32 -> fp16 per batch: out[l][s] = in[s][l]
// ---------------------------------------------------------------------------
__global__ __launch_bounds__(256, 2) void prep_t(
    const float* __restrict__ in, __half* __restrict__ out) {
  __shared__ float t[64][65];
  const int z = blockIdx.z;
  const int r0 = blockIdx.y * 64, c0 = blockIdx.x * 64;
  const int tid = threadIdx.x;
  const size_t base = (size_t)z * 1024 * 1024;
  const int tr = tid >> 4, tc4 = (tid & 15) * 4;
#pragma unroll
  for (int i = 0; i < 4; i++) {
    int row = tr + i * 16;
    float4 v = *(const float4*)&in[base + (size_t)(r0 + row) * 1024 + c0 + tc4];
    t[row][tc4+0] = v.x; t[row][tc4+1] = v.y;
    t[row][tc4+2] = v.z; t[row][tc4+3] = v.w;
  }
  __syncthreads();
#pragma unroll
  for (int i = 0; i < 4; i++) {
    int orow = tr + i * 16;
    uint2 u;
    u.x = f2h2(t[tc4+0][orow], t[tc4+1][orow]);
    u.y = f2h2(t[tc4+2][orow], t[tc4+3][orow]);
    *(uint2*)&out[base + (size_t)(c0 + orow) * 1024 + r0 + tc4] = u;
  }
}

// ---------------------------------------------------------------------------
// proj: C[b] = W (fp16 row-major) @ X[b] + bias, X transposed fp16 (Xt[l][s]).
// Tile 128x128, k-step 32, DOUBLE-BUFFERED smem, 1 sync per k-step.
// fp32_out=1: fp32 C[s][l].  fp32_out=0: fp16 per-head Tout[bh][l][d].
// ---------------------------------------------------------------------------
__global__ __launch_bounds__(256, 2) void proj_h(
    const __half* __restrict__ Wh, const __half* __restrict__ Xt,
    const float* __restrict__ bias, float* __restrict__ Cout,
    __half* __restrict__ Tout, int fp32_out) {
  extern __shared__ __half psm[];
  __half* As = psm;              // [2][128*40]
  __half* Bs = psm + 10240;      // [2][128*40]
  unsigned* As2 = (unsigned*)As;
  unsigned* Bs2 = (unsigned*)Bs;
  const int b = blockIdx.z;
  const int row0 = blockIdx.y*128, col0 = blockIdx.x*128;
  const __half* Xb = Xt + (size_t)b*1024*1024;
  const int tid = threadIdx.x, wid = tid>>5, lane = tid&31;
  const int gi = lane>>2, tj = lane&3;
  const int wm = (wid>>2)*64, wn = (wid&3)*32;
  const int r = tid>>1, sg = (tid&1)*16;

  float acc[4][4][4] = {};
  uint4 pa0, pa1, pb0, pb1;
  {
    const uint4* sa = (const uint4*)&Wh[(size_t)(row0 + r)*1024 + sg];
    pa0 = sa[0]; pa1 = sa[1];
    const uint4* sb = (const uint4*)&Xb[(size_t)(col0 + r)*1024 + sg];
    pb0 = sb[0]; pb1 = sb[1];
  }
  {
    uint4* da = (uint4*)&As[r*40 + sg];
    da[0] = pa0; da[1] = pa1;
    uint4* db = (uint4*)&Bs[r*40 + sg];
    db[0] = pb0; db[1] = pb1;
  }
  __syncthreads();

  for (int s = 0; s < 32; s++) {
    const int cur = s & 1, nxt = cur ^ 1;
    if (s < 31) {
      int k0 = (s + 1) * 32;
      const uint4* sa = (const uint4*)&Wh[(size_t)(row0 + r)*1024 + k0 + sg];
      pa0 = sa[0]; pa1 = sa[1];
      const uint4* sb = (const uint4*)&Xb[(size_t)(col0 + r)*1024 + k0 + sg];
      pb0 = sb[0]; pb1 = sb[1];
    }
#pragma unroll
    for (int c = 0; c < 2; c++) {
      unsigned a[4][4], bb[4][2];
#pragma unroll
      for (int mt = 0; mt < 4; mt++) {
        int base = cur*2560 + (wm + mt*16 + gi)*20 + c*8 + tj;
        a[mt][0] = As2[base];
        a[mt][1] = As2[base + 160];
        a[mt][2] = As2[base + 4];
        a[mt][3] = As2[base + 164];
      }
#pragma unroll
      for (int nt = 0; nt < 4; nt++) {
        int nb = cur*2560 + (wn + nt*8 + gi)*20 + c*8 + tj;
        bb[nt][0] = Bs2[nb];
        bb[nt][1] = Bs2[nb + 4];
      }
#pragma unroll
      for (int mt = 0; mt < 4; mt++)
#pragma unroll
        for (int nt = 0; nt < 4; nt++)
          mma16(acc[mt][nt], a[mt][0],a[mt][1],a[mt][2],a[mt][3],
                bb[nt][0], bb[nt][1]);
    }
    if (s < 31) {
      uint4* da = (uint4*)&As[nxt*5120 + r*40 + sg];
      da[0] = pa0; da[1] = pa1;
      uint4* db = (uint4*)&Bs[nxt*5120 + r*40 + sg];
      db[0] = pb0; db[1] = pb1;
    }
    __syncthreads();
  }

  if (fp32_out) {
    float* Cb = Cout + (size_t)b*1024*1024;
#pragma unroll
    for (int mt = 0; mt < 4; mt++) {
      int r0_ = row0 + wm + mt*16 + gi;
      float bv0 = bias[r0_], bv1 = bias[r0_+8];
#pragma unroll
      for (int nt = 0; nt < 4; nt++) {
        int cc = col0 + wn + nt*8 + 2*tj;
        *(float2*)&Cb[(size_t)r0_*1024 + cc] =
            make_float2(acc[mt][nt][0]+bv0, acc[mt][nt][1]+bv0);
        *(float2*)&Cb[(size_t)(r0_+8)*1024 + cc] =
            make_float2(acc[mt][nt][2]+bv1, acc[mt][nt][3]+bv1);
      }
    }
  } else {
    __half* Cts = psm;   // 128*136 halves (fits in 20480-half As region)
    __syncthreads();
#pragma unroll
    for (int mt = 0; mt < 4; mt++) {
      int r_ = wm + mt*16 + gi;
      float bv0 = bias[row0 + r_], bv1 = bias[row0 + r_ + 8];
#pragma unroll
      for (int nt = 0; nt < 4; nt++) {
        int c_ = wn + nt*8 + 2*tj;
        Cts[c_*136 + r_]       = __float2half(acc[mt][nt][0] + bv0);
        Cts[(c_+1)*136 + r_]   = __float2half(acc[mt][nt][1] + bv0);
        Cts[c_*136 + r_+8]     = __float2half(acc[mt][nt][2] + bv1);
        Cts[(c_+1)*136 + r_+8] = __float2half(acc[mt][nt][3] + bv1);
      }
    }
    __syncthreads();
    int l = tid>>1, part = tid&1;
    size_t obase = ((size_t)(b*16 + (row0>>6) + part)*1024 + col0 + l)*64;
#pragma unroll
    for (int j = 0; j < 8; j++)
      *(uint4*)&Tout[obase + j*8] = *(const uint4*)&Cts[l*136 + part*64 + j*8];
  }
}

// ---------------------------------------------------------------------------
// zpass: Z[l] = sum_m exp(S[l,m]/tau).  S^T[m][l] = Q^T K tiles.
// Block (bh, 128-l tile); m in 128 chunks; Q double-buffered, 1 sync/iter.
// ---------------------------------------------------------------------------
__global__ __launch_bounds__(256, 2) void zpass_h(
    const __half* __restrict__ Kt, const __half* __restrict__ Qt,
    float* __restrict__ Z) {
  extern __shared__ __half zsm[];
  __half* Ks = zsm;             // 128*72
  __half* Qs = zsm + 9216;      // [2][128*72]
  float* Zp = (float*)(zsm + 27648);  // 256 floats
  unsigned* Ks2 = (unsigned*)Ks;
  unsigned* Qs2 = (unsigned*)Qs;
  const int bh = blockIdx.y, l0 = blockIdx.x*128;
  const __half* Kb = Kt + (size_t)bh*65536;
  const __half* Qb = Qt + (size_t)bh*65536;
  const int tid = threadIdx.x, wid = tid>>5, lane = tid&31;
  const int gi = lane>>2, tj = lane&3;
  const int wm_ = (wid>>2)*64, wl_ = (wid&3)*32;
  const int r = tid>>1, sg = (tid&1)*32;

  {
    const uint4* s = (const uint4*)&Kb[(size_t)(l0 + r)*64 + sg];
    uint4* d = (uint4*)&Ks[r*72 + sg];
    d[0]=s[0]; d[1]=s[1]; d[2]=s[2]; d[3]=s[3];
  }
  uint4 pq[4];
  {
    const uint4* s = (const uint4*)&Qb[(size_t)r*64 + sg];
    pq[0]=s[0]; pq[1]=s[1]; pq[2]=s[2]; pq[3]=s[3];
    uint4* d = (uint4*)&Qs[r*72 + sg];
    d[0]=pq[0]; d[1]=pq[1]; d[2]=pq[2]; d[3]=pq[3];
  }
  __syncthreads();

  float rs[4][2] = {};
  for (int m0 = 0; m0 < 1024; m0 += 128) {
    const int cur = (m0 >> 7) & 1, nxt = cur ^ 1;
    if (m0 < 896) {
      const uint4* s = (const uint4*)&Qb[(size_t)(m0 + 128 + r)*64 + sg];
      pq[0]=s[0]; pq[1]=s[1]; pq[2]=s[2]; pq[3]=s[3];
    }
    float S[4][4][4] = {};
#pragma unroll
    for (int c = 0; c < 4; c++) {
      unsigned a[4][4], bb[4][2];
#pragma unroll
      for (int mt = 0; mt < 4; mt++) {
        int base = cur*4608 + (wm_ + mt*16 + gi)*36 + c*8 + tj;
        a[mt][0] = Qs2[base];
        a[mt][1] = Qs2[base + 288];
        a[mt][2] = Qs2[base + 4];
        a[mt][3] = Qs2[base + 292];
      }
#pragma unroll
      for (int nt = 0; nt < 4; nt++) {
        int nb = (wl_ + nt*8 + gi)*36 + c*8 + tj;
        bb[nt][0] = Ks2[nb];
        bb[nt][1] = Ks2[nb + 4];
      }
#pragma unroll
      for (int mt = 0; mt < 4; mt++)
#pragma unroll
        for (int nt = 0; nt < 4; nt++)
          mma16(S[mt][nt], a[mt][0],a[mt][1],a[mt][2],a[mt][3],
                bb[nt][0], bb[nt][1]);
    }
#pragma unroll
    for (int mt = 0; mt < 4; mt++)
#pragma unroll
      for (int nt = 0; nt < 4; nt++) {
        rs[nt][0] += __expf(S[mt][nt][0]*INV_TAU) + __expf(S[mt][nt][2]*INV_TAU);
        rs[nt][1] += __expf(S[mt][nt][1]*INV_TAU) + __expf(S[mt][nt][3]*INV_TAU);
      }
    if (m0 < 896) {
      uint4* d = (uint4*)&Qs[nxt*9216 + r*72 + sg];
      d[0]=pq[0]; d[1]=pq[1]; d[2]=pq[2]; d[3]=pq[3];
    }
    __syncthreads();
  }
#pragma unroll
  for (int nt = 0; nt < 4; nt++)
#pragma unroll
    for (int j = 0; j < 2; j++) {
      float v = rs[nt][j];
      v += __shfl_xor_sync(0xffffffffu, v, 4);
      v += __shfl_xor_sync(0xffffffffu, v, 8);
      v += __shfl_xor_sync(0xffffffffu, v, 16);
      rs[nt][j] = v;
    }
  if (gi == 0) {
#pragma unroll
    for (int nt = 0; nt < 4; nt++)
#pragma unroll
      for (int j = 0; j < 2; j++)
        Zp[(wid>>2)*128 + wl_ + nt*8 + 2*tj + j] = rs[nt][j];
  }
  __syncthreads();
  if (tid < 128)
    Z[(size_t)bh*1024 + l0 + tid] = Zp[tid] + Zp[128 + tid];
}

// ---------------------------------------------------------------------------
// opass: O[d,m] = sum_l (x[d,l]/Z[l]) * exp(S[l,m]/tau).
// GEMM1: S^T[m][l]; P in [m][l]; GEMM2: O[d][m] via B=Ps rows. Out Ot[m][s].
// K and X both register-prefetched (X from fp16 copy).
// ---------------------------------------------------------------------------
__global__ __launch_bounds__(256, 2) void opass_h(
    const __half* __restrict__ X16, const __half* __restrict__ Kt,
    const __half* __restrict__ Qt, const float* __restrict__ Z,
    __half* __restrict__ Ot) {
  extern __shared__ __half osm[];
  __half* Qs = osm;             // 128*72 = 9216 halves
  __half* Ks = osm + 9216;      // 64*72 = 4608
  __half* Xs = osm + 13824;     // 64*72 = 4608
  __half* Ps = osm + 18432;     // 128*72 = 9216
  float* Zr = (float*)(osm + 27648);  // 1024 floats
  unsigned* Qs2 = (unsigned*)Qs;
  unsigned* Ks2 = (unsigned*)Ks;
  unsigned* Xs2 = (unsigned*)Xs;
  unsigned* Ps2 = (unsigned*)Ps;
  const int bh = blockIdx.y, m0 = blockIdx.x*128;
  const int b = bh>>4, h = bh&15;
  const __half* Kb = Kt + (size_t)bh*65536;
  const __half* Qb = Qt + (size_t)bh*65536;
  const __half* Xh = X16 + ((size_t)b*1024 + h*64)*1024;
  const int tid = threadIdx.x, wid = tid>>5, lane = tid&31;
  const int gi = lane>>2, tj = lane&3;
  const int wm1 = (wid>>2)*64, wl1 = (wid&3)*16;   // GEMM1 warp tile
  const int wr2 = (wid>>2)*32, wn2 = (wid&3)*32;   // GEMM2 warp tile
  const int rk = tid>>2, ck = (tid&3)*16;          // K/X load pattern

  {
    int r = tid>>1, sg = (tid&1)*32;
    const uint4* s = (const uint4*)&Qb[(size_t)(m0 + r)*64 + sg];
    uint4* d = (uint4*)&Qs[r*72 + sg];
    d[0]=s[0]; d[1]=s[1]; d[2]=s[2]; d[3]=s[3];
  }
  {
    float4 z = *(const float4*)&Z[(size_t)bh*1024 + tid*4];
    Zr[tid*4+0] = __frcp_rn(z.x);
    Zr[tid*4+1] = __frcp_rn(z.y);
    Zr[tid*4+2] = __frcp_rn(z.z);
    Zr[tid*4+3] = __frcp_rn(z.w);
  }
  __syncthreads();

  float O[2][4][4] = {};
  uint4 pk0, pk1, px0, px1;
  {
    const uint4* s = (const uint4*)&Kb[(size_t)rk*64 + ck];
    pk0 = s[0]; pk1 = s[1];
    const uint4* t = (const uint4*)&Xh[(size_t)rk*1024 + ck];
    px0 = t[0]; px1 = t[1];
  }

  for (int l0 = 0; l0 < 1024; l0 += 64) {
    __syncthreads();
    {
      uint4* d = (uint4*)&Ks[rk*72 + ck];
      d[0] = pk0; d[1] = pk1;
      // X: fp16 pairs * Zr (fp32) -> fp16
      unsigned pxw[8] = {px0.x, px0.y, px0.z, px0.w, px1.x, px1.y, px1.z, px1.w};
#pragma unroll
      for (int j = 0; j < 8; j++) {
        __half2 hv = *(__half2*)&pxw[j];
        float2 f = __half22float2(hv);
        f.x *= Zr[l0 + ck + 2*j];
        f.y *= Zr[l0 + ck + 2*j + 1];
        Xs2[rk*36 + (ck>>1) + j] = f2h2(f.x, f.y);
      }
    }
    __syncthreads();
    if (l0 < 960) {
      const uint4* s = (const uint4*)&Kb[(size_t)(l0 + 64 + rk)*64 + ck];
      pk0 = s[0]; pk1 = s[1];
      const uint4* t = (const uint4*)&Xh[(size_t)rk*1024 + l0 + 64 + ck];
      px0 = t[0]; px1 = t[1];
    }
    // GEMM1: S^T[m 128][l 64] = Q^T K
    float S[4][2][4] = {};
#pragma unroll
    for (int c = 0; c < 4; c++) {
      unsigned a[4][4], bb[2][2];
#pragma unroll
      for (int mt = 0; mt < 4; mt++) {
        int base = (wm1 + mt*16 + gi)*36 + c*8 + tj;
        a[mt][0] = Qs2[base];
        a[mt][1] = Qs2[base + 288];
        a[mt][2] = Qs2[base + 4];
        a[mt][3] = Qs2[base + 292];
      }
#pragma unroll
      for (int nt = 0; nt < 2; nt++) {
        int nb = (wl1 + nt*8 + gi)*36 + c*8 + tj;
        bb[nt][0] = Ks2[nb];
        bb[nt][1] = Ks2[nb + 4];
      }
#pragma unroll
      for (int mt = 0; mt < 4; mt++)
#pragma unroll
        for (int nt = 0; nt < 2; nt++)
          mma16(S[mt][nt], a[mt][0],a[mt][1],a[mt][2],a[mt][3],
                bb[nt][0], bb[nt][1]);
    }
    // exp -> Ps[m][l] (half2 vectorized)
#pragma unroll
    for (int mt = 0; mt < 4; mt++) {
      int m_ = wm1 + mt*16 + gi;
#pragma unroll
      for (int nt = 0; nt < 2; nt++) {
        int lu = wl1/2 + nt*4 + tj;
        Ps2[m_*36 + lu] =
            f2h2(__expf(S[mt][nt][0]*INV_TAU), __expf(S[mt][nt][1]*INV_TAU));
        Ps2[(m_+8)*36 + lu] =
            f2h2(__expf(S[mt][nt][2]*INV_TAU), __expf(S[mt][nt][3]*INV_TAU));
      }
    }
    __syncthreads();
    // GEMM2: O[d 64][m 128] += X'[d][l] @ P^T
#pragma unroll
    for (int c = 0; c < 4; c++) {
      unsigned a[2][4], bb[4][2];
#pragma unroll
      for (int mt = 0; mt < 2; mt++) {
        int base = (wr2 + mt*16 + gi)*36 + c*8 + tj;
        a[mt][0] = Xs2[base];
        a[mt][1] = Xs2[base + 288];
        a[mt][2] = Xs2[base + 4];
        a[mt][3] = Xs2[base + 292];
      }
#pragma unroll
      for (int nt = 0; nt < 4; nt++) {
        int nb = (wn2 + nt*8 + gi)*36 + c*8 + tj;
        bb[nt][0] = Ps2[nb];
        bb[nt][1] = Ps2[nb + 4];
      }
#pragma unroll
      for (int mt = 0; mt < 2; mt++)
#pragma unroll
        for (int nt = 0; nt < 4; nt++)
          mma16(O[mt][nt], a[mt][0],a[mt][1],a[mt][2],a[mt][3],
                bb[nt][0], bb[nt][1]);
    }
  }
  // Epilogue: stage Os[m 128][d 64] (stride 72) over Qs, coalesced write
  __syncthreads();
  __half* Os = Qs;
#pragma unroll
  for (int mt = 0; mt < 2; mt++) {
    int d_ = wr2 + mt*16 + gi;
#pragma unroll
    for (int nt = 0; nt < 4; nt++) {
      int m_ = wn2 + nt*8 + 2*tj;
      Os[m_*72 + d_]       = __float2half(O[mt][nt][0]);
      Os[(m_+1)*72 + d_]   = __float2half(O[mt][nt][1]);
      Os[m_*72 + d_+8]     = __float2half(O[mt][nt][2]);
      Os[(m_+1)*72 + d_+8] = __float2half(O[mt][nt][3]);
    }
  }
  __syncthreads();
  {
    int m = tid>>1, sg = (tid&1)*32;
    const uint4* s = (const uint4*)&Os[m*72 + sg];
    uint4 v0 = s[0], v1 = s[1], v2 = s[2], v3 = s[3];
    __half* dst = &Ot[((size_t)b*1024 + m0 + m)*1024 + h*64 + sg];
    *(uint4*)dst        = v0;
    *(uint4*)(dst + 8)  = v1;
    *(uint4*)(dst + 16) = v2;
    *(uint4*)(dst + 24) = v3;
  }
}

// ---------------------------------------------------------------------------
extern "C" void kernel_launch(void* const* d_in, const int* in_sizes, int n_in,
                              void* d_out, int out_size) {
  (void)in_sizes; (void)n_in; (void)out_size;
  const float* x  = (const float*)d_in[0];
  const float* y  = (const float*)d_in[1];
  const float* Wk = (const float*)d_in[2];
  const float* bk = (const float*)d_in[3];
  const float* Wq = (const float*)d_in[4];
  const float* bq = (const float*)d_in[5];
  const float* Wp = (const float*)d_in[6];
  const float* bp = (const float*)d_in[7];
  float* out = (float*)d_out;

  __half *Xt, *Yt, *Otp, *X16, *Wh, *Ktp, *Qtp; float* Zp;
  cudaGetSymbolAddress((void**)&Xt,  g_Xt);
  cudaGetSymbolAddress((void**)&Yt,  g_Yt);
  cudaGetSymbolAddress((void**)&Otp, g_Ot);
  cudaGetSymbolAddress((void**)&X16, g_X16);
  cudaGetSymbolAddress((void**)&Wh,  g_Wh);
  cudaGetSymbolAddress((void**)&Ktp, g_Kt);
  cudaGetSymbolAddress((void**)&Qtp, g_Qt);
  cudaGetSymbolAddress((void**)&Zp,  g_Z);

  const int psmem = 2*20480;                      // 40,960 B (dbl buf / Cts)
  const int zsmem = 27648*2 + 1024;               // 56,320 B
  const int osmem = (9216+4608+4608+9216)*2 + 1024*4;  // 59,392 B
  cudaFuncSetAttribute(proj_h,  cudaFuncAttributeMaxDynamicSharedMemorySize, psmem);
  cudaFuncSetAttribute(zpass_h, cudaFuncAttributeMaxDynamicSharedMemorySize, zsmem);
  cudaFuncSetAttribute(opass_h, cudaFuncAttributeMaxDynamicSharedMemorySize, osmem);

  dim3 tg(16, 16, 8), pg(8, 8, 8);
  cvt16<<<1024, 256>>>(Wk, Wh);
  cvt16<<<1024, 256>>>(Wq, Wh + 1024*1024);
  cvt16<<<1024, 256>>>(Wp, Wh + 2ul*1024*1024);
  cvt16<<<8192, 256>>>(x, X16);
  prep_t<<<tg, 256>>>(x, Xt);
  prep_t<<<tg, 256>>>(y, Yt);
  proj_h<<<pg, 256, psmem>>>(Wh, Xt, bk, nullptr, Ktp, 0);
  proj_h<<<pg, 256, psmem>>>(Wh + 1024*1024, Yt, bq, nullptr, Qtp, 0);
  zpass_h<<<dim3(8, 128), 256, zsmem>>>(Ktp, Qtp, Zp);
  opass_h<<<dim3(8, 128), 256, osmem>>>(X16, Ktp, Qtp, Zp, Otp);
  proj_h<<<pg, 256, psmem>>>(Wh + 2ul*1024*1024, Otp, bp, out, nullptr, 1);
}

// round 13
// speedup vs baseline: 3.9769x; 1.0794x over previous
#include <cuda_runtime.h>
#include <cuda_fp16.h>

#define INV_TAU (1.0f/512.0f)

// Scratch (no cudaMalloc allowed)
__device__ __half g_Xt[8ul*1024*1024];     // x^T fp16 [b][l][s]
__device__ __half g_Yt[8ul*1024*1024];     // y^T fp16 [b][l][s]
__device__ __half g_Ot[8ul*1024*1024];     // O^T fp16 [b][m][s]
__device__ __half g_X16[8ul*1024*1024];    // x fp16 [b][s][l]
__device__ __half g_Wh[3ul*1024*1024];     // Wk,Wq,Wp fp16 row-major
__device__ __half g_Kt[128ul*1024*64];     // K^T fp16 [bh][l][d]
__device__ __half g_Qt[128ul*1024*64];     // Q^T fp16 [bh][m][d]
__device__ float  g_Z[128ul*1024];

__device__ __forceinline__ unsigned f2h2(float a, float b) {
  __half2 h = __floats2half2_rn(a, b);
  return *(unsigned*)&h;
}

__device__ __forceinline__ unsigned su32(const void* p) {
  unsigned a;
  asm("{ .reg .u64 t; cvta.to.shared.u64 t, %1; cvt.u32.u64 %0, t; }"
      : "=r"(a) : "l"(p));
  return a;
}

__device__ __forceinline__ void mma16(float* c, unsigned a0, unsigned a1,
                                      unsigned a2, unsigned a3,
                                      unsigned b0, unsigned b1) {
  asm("mma.sync.aligned.m16n8k16.row.col.f32.f16.f16.f32 "
      "{%0,%1,%2,%3}, {%4,%5,%6,%7}, {%8,%9}, {%0,%1,%2,%3};"
      : "+f"(c[0]), "+f"(c[1]), "+f"(c[2]), "+f"(c[3])
      : "r"(a0), "r"(a1), "r"(a2), "r"(a3), "r"(b0), "r"(b1));
}

#define LDSM4(r0, r1, r2, r3, addr) \
  asm volatile("ldmatrix.sync.aligned.m8n8.x4.shared.b16 {%0,%1,%2,%3}, [%4];" \
               : "=r"(r0), "=r"(r1), "=r"(r2), "=r"(r3) : "r"(addr))

// ---------------------------------------------------------------------------
__global__ __launch_bounds__(256) void cvt16(
    const float* __restrict__ in, __half* __restrict__ out) {
  size_t i = ((size_t)blockIdx.x*256 + threadIdx.x)*4;
  float4 v = *(const float4*)&in[i];
  *(uint2*)&out[i] = make_uint2(f2h2(v.x, v.y), f2h2(v.z, v.w));
}

// ---------------------------------------------------------------------------
__global__ __launch_bounds__(256, 2) void prep_t(
    const float* __restrict__ in, __half* __restrict__ out) {
  __shared__ float t[64][65];
  const int z = blockIdx.z;
  const int r0 = blockIdx.y * 64, c0 = blockIdx.x * 64;
  const int tid = threadIdx.x;
  const size_t base = (size_t)z * 1024 * 1024;
  const int tr = tid >> 4, tc4 = (tid & 15) * 4;
#pragma unroll
  for (int i = 0; i < 4; i++) {
    int row = tr + i * 16;
    float4 v = *(const float4*)&in[base + (size_t)(r0 + row) * 1024 + c0 + tc4];
    t[row][tc4+0] = v.x; t[row][tc4+1] = v.y;
    t[row][tc4+2] = v.z; t[row][tc4+3] = v.w;
  }
  __syncthreads();
#pragma unroll
  for (int i = 0; i < 4; i++) {
    int orow = tr + i * 16;
    uint2 u;
    u.x = f2h2(t[tc4+0][orow], t[tc4+1][orow]);
    u.y = f2h2(t[tc4+2][orow], t[tc4+3][orow]);
    *(uint2*)&out[base + (size_t)(c0 + orow) * 1024 + r0 + tc4] = u;
  }
}

// ---------------------------------------------------------------------------
// proj: C[b] = W fp16 @ X[b] + bias (Xt[l][s] fp16). 128x128 tile, k-step 32,
// double-buffered, ldmatrix fragment loads.
// ---------------------------------------------------------------------------
__global__ __launch_bounds__(256, 2) void proj_h(
    const __half* __restrict__ Wh, const __half* __restrict__ Xt,
    const float* __restrict__ bias, float* __restrict__ Cout,
    __half* __restrict__ Tout, int fp32_out) {
  extern __shared__ __half psm[];
  __half* As = psm;              // [2][128*40]
  __half* Bs = psm + 10240;      // [2][128*40]
  const int b = blockIdx.z;
  const int row0 = blockIdx.y*128, col0 = blockIdx.x*128;
  const __half* Xb = Xt + (size_t)b*1024*1024;
  const int tid = threadIdx.x, wid = tid>>5, lane = tid&31;
  const int gi = lane>>2, tj = lane&3;
  const int wm = (wid>>2)*64, wn = (wid&3)*32;
  const int r = tid>>1, sg = (tid&1)*16;
  const unsigned smA = su32(As), smB = su32(Bs);
  const int laneA = (((lane&7) + ((lane>>3)&1)*8)*40 + ((lane>>4)&1)*8)*2;
  const int laneB = (((lane&7) + ((lane>>4)&1)*8)*40 + ((lane>>3)&1)*8)*2;

  float acc[4][4][4] = {};
  uint4 pa0, pa1, pb0, pb1;
  {
    const uint4* sa = (const uint4*)&Wh[(size_t)(row0 + r)*1024 + sg];
    pa0 = sa[0]; pa1 = sa[1];
    const uint4* sb = (const uint4*)&Xb[(size_t)(col0 + r)*1024 + sg];
    pb0 = sb[0]; pb1 = sb[1];
  }
  {
    uint4* da = (uint4*)&As[r*40 + sg];
    da[0] = pa0; da[1] = pa1;
    uint4* db = (uint4*)&Bs[r*40 + sg];
    db[0] = pb0; db[1] = pb1;
  }
  __syncthreads();

  for (int s = 0; s < 32; s++) {
    const int cur = s & 1, nxt = cur ^ 1;
    if (s < 31) {
      int k0 = (s + 1) * 32;
      const uint4* sa = (const uint4*)&Wh[(size_t)(row0 + r)*1024 + k0 + sg];
      pa0 = sa[0]; pa1 = sa[1];
      const uint4* sb = (const uint4*)&Xb[(size_t)(col0 + r)*1024 + k0 + sg];
      pb0 = sb[0]; pb1 = sb[1];
    }
#pragma unroll
    for (int c = 0; c < 2; c++) {
      unsigned a[4][4], bb[4][2];
#pragma unroll
      for (int mt = 0; mt < 4; mt++)
        LDSM4(a[mt][0], a[mt][1], a[mt][2], a[mt][3],
              smA + cur*10240 + ((wm + mt*16)*40 + c*16)*2 + laneA);
      LDSM4(bb[0][0], bb[0][1], bb[1][0], bb[1][1],
            smB + cur*10240 + (wn*40 + c*16)*2 + laneB);
      LDSM4(bb[2][0], bb[2][1], bb[3][0], bb[3][1],
            smB + cur*10240 + ((wn + 16)*40 + c*16)*2 + laneB);
#pragma unroll
      for (int mt = 0; mt < 4; mt++)
#pragma unroll
        for (int nt = 0; nt < 4; nt++)
          mma16(acc[mt][nt], a[mt][0],a[mt][1],a[mt][2],a[mt][3],
                bb[nt][0], bb[nt][1]);
    }
    if (s < 31) {
      uint4* da = (uint4*)&As[nxt*5120 + r*40 + sg];
      da[0] = pa0; da[1] = pa1;
      uint4* db = (uint4*)&Bs[nxt*5120 + r*40 + sg];
      db[0] = pb0; db[1] = pb1;
    }
    __syncthreads();
  }

  if (fp32_out) {
    float* Cb = Cout + (size_t)b*1024*1024;
#pragma unroll
    for (int mt = 0; mt < 4; mt++) {
      int r0_ = row0 + wm + mt*16 + gi;
      float bv0 = bias[r0_], bv1 = bias[r0_+8];
#pragma unroll
      for (int nt = 0; nt < 4; nt++) {
        int cc = col0 + wn + nt*8 + 2*tj;
        *(float2*)&Cb[(size_t)r0_*1024 + cc] =
            make_float2(acc[mt][nt][0]+bv0, acc[mt][nt][1]+bv0);
        *(float2*)&Cb[(size_t)(r0_+8)*1024 + cc] =
            make_float2(acc[mt][nt][2]+bv1, acc[mt][nt][3]+bv1);
      }
    }
  } else {
    __half* Cts = psm;   // 128*136 halves
    __syncthreads();
#pragma unroll
    for (int mt = 0; mt < 4; mt++) {
      int r_ = wm + mt*16 + gi;
      float bv0 = bias[row0 + r_], bv1 = bias[row0 + r_ + 8];
#pragma unroll
      for (int nt = 0; nt < 4; nt++) {
        int c_ = wn + nt*8 + 2*tj;
        Cts[c_*136 + r_]       = __float2half(acc[mt][nt][0] + bv0);
        Cts[(c_+1)*136 + r_]   = __float2half(acc[mt][nt][1] + bv0);
        Cts[c_*136 + r_+8]     = __float2half(acc[mt][nt][2] + bv1);
        Cts[(c_+1)*136 + r_+8] = __float2half(acc[mt][nt][3] + bv1);
      }
    }
    __syncthreads();
    int l = tid>>1, part = tid&1;
    size_t obase = ((size_t)(b*16 + (row0>>6) + part)*1024 + col0 + l)*64;
#pragma unroll
    for (int j = 0; j < 8; j++)
      *(uint4*)&Tout[obase + j*8] = *(const uint4*)&Cts[l*136 + part*64 + j*8];
  }
}

// ---------------------------------------------------------------------------
// zpass: Z[l] = sum_m exp(S[l,m]/tau).  S^T[m][l] = Q^T K; ldmatrix loads.
// ---------------------------------------------------------------------------
__global__ __launch_bounds__(256, 2) void zpass_h(
    const __half* __restrict__ Kt, const __half* __restrict__ Qt,
    float* __restrict__ Z) {
  extern __shared__ __half zsm[];
  __half* Ks = zsm;             // 128*72
  __half* Qs = zsm + 9216;      // [2][128*72]
  float* Zp = (float*)(zsm + 27648);
  const int bh = blockIdx.y, l0 = blockIdx.x*128;
  const __half* Kb = Kt + (size_t)bh*65536;
  const __half* Qb = Qt + (size_t)bh*65536;
  const int tid = threadIdx.x, wid = tid>>5, lane = tid&31;
  const int gi = lane>>2, tj = lane&3;
  const int wm_ = (wid>>2)*64, wl_ = (wid&3)*32;
  const int r = tid>>1, sg = (tid&1)*32;
  const unsigned smK = su32(Ks), smQ = su32(Qs);
  const int laneA = (((lane&7) + ((lane>>3)&1)*8)*72 + ((lane>>4)&1)*8)*2;
  const int laneB = (((lane&7) + ((lane>>4)&1)*8)*72 + ((lane>>3)&1)*8)*2;

  {
    const uint4* s = (const uint4*)&Kb[(size_t)(l0 + r)*64 + sg];
    uint4* d = (uint4*)&Ks[r*72 + sg];
    d[0]=s[0]; d[1]=s[1]; d[2]=s[2]; d[3]=s[3];
  }
  uint4 pq[4];
  {
    const uint4* s = (const uint4*)&Qb[(size_t)r*64 + sg];
    pq[0]=s[0]; pq[1]=s[1]; pq[2]=s[2]; pq[3]=s[3];
    uint4* d = (uint4*)&Qs[r*72 + sg];
    d[0]=pq[0]; d[1]=pq[1]; d[2]=pq[2]; d[3]=pq[3];
  }
  __syncthreads();

  float rs[4][2] = {};
  for (int m0 = 0; m0 < 1024; m0 += 128) {
    const int cur = (m0 >> 7) & 1, nxt = cur ^ 1;
    if (m0 < 896) {
      const uint4* s = (const uint4*)&Qb[(size_t)(m0 + 128 + r)*64 + sg];
      pq[0]=s[0]; pq[1]=s[1]; pq[2]=s[2]; pq[3]=s[3];
    }
    float S[4][4][4] = {};
#pragma unroll
    for (int c = 0; c < 4; c++) {
      unsigned a[4][4], bb[4][2];
#pragma unroll
      for (int mt = 0; mt < 4; mt++)
        LDSM4(a[mt][0], a[mt][1], a[mt][2], a[mt][3],
              smQ + cur*18432 + ((wm_ + mt*16)*72 + c*16)*2 + laneA);
      LDSM4(bb[0][0], bb[0][1], bb[1][0], bb[1][1],
            smK + (wl_*72 + c*16)*2 + laneB);
      LDSM4(bb[2][0], bb[2][1], bb[3][0], bb[3][1],
            smK + ((wl_ + 16)*72 + c*16)*2 + laneB);
#pragma unroll
      for (int mt = 0; mt < 4; mt++)
#pragma unroll
        for (int nt = 0; nt < 4; nt++)
          mma16(S[mt][nt], a[mt][0],a[mt][1],a[mt][2],a[mt][3],
                bb[nt][0], bb[nt][1]);
    }
#pragma unroll
    for (int mt = 0; mt < 4; mt++)
#pragma unroll
      for (int nt = 0; nt < 4; nt++) {
        rs[nt][0] += __expf(S[mt][nt][0]*INV_TAU) + __expf(S[mt][nt][2]*INV_TAU);
        rs[nt][1] += __expf(S[mt][nt][1]*INV_TAU) + __expf(S[mt][nt][3]*INV_TAU);
      }
    if (m0 < 896) {
      uint4* d = (uint4*)&Qs[nxt*9216 + r*72 + sg];
      d[0]=pq[0]; d[1]=pq[1]; d[2]=pq[2]; d[3]=pq[3];
    }
    __syncthreads();
  }
#pragma unroll
  for (int nt = 0; nt < 4; nt++)
#pragma unroll
    for (int j = 0; j < 2; j++) {
      float v = rs[nt][j];
      v += __shfl_xor_sync(0xffffffffu, v, 4);
      v += __shfl_xor_sync(0xffffffffu, v, 8);
      v += __shfl_xor_sync(0xffffffffu, v, 16);
      rs[nt][j] = v;
    }
  if (gi == 0) {
#pragma unroll
    for (int nt = 0; nt < 4; nt++)
#pragma unroll
      for (int j = 0; j < 2; j++)
        Zp[(wid>>2)*128 + wl_ + nt*8 + 2*tj + j] = rs[nt][j];
  }
  __syncthreads();
  if (tid < 128)
    Z[(size_t)bh*1024 + l0 + tid] = Zp[tid] + Zp[128 + tid];
}

// ---------------------------------------------------------------------------
// opass: O[d,m] = sum_l (x[d,l]/Z[l]) * exp(S[l,m]/tau); ldmatrix loads.
// ---------------------------------------------------------------------------
__global__ __launch_bounds__(256, 2) void opass_h(
    const __half* __restrict__ X16, const __half* __restrict__ Kt,
    const __half* __restrict__ Qt, const float* __restrict__ Z,
    __half* __restrict__ Ot) {
  extern __shared__ __half osm[];
  __half* Qs = osm;             // 128*72
  __half* Ks = osm + 9216;      // 64*72
  __half* Xs = osm + 13824;     // 64*72
  __half* Ps = osm + 18432;     // 128*72
  float* Zr = (float*)(osm + 27648);
  unsigned* Xs2 = (unsigned*)Xs;
  unsigned* Ps2 = (unsigned*)Ps;
  const int bh = blockIdx.y, m0 = blockIdx.x*128;
  const int b = bh>>4, h = bh&15;
  const __half* Kb = Kt + (size_t)bh*65536;
  const __half* Qb = Qt + (size_t)bh*65536;
  const __half* Xh = X16 + ((size_t)b*1024 + h*64)*1024;
  const int tid = threadIdx.x, wid = tid>>5, lane = tid&31;
  const int gi = lane>>2, tj = lane&3;
  const int wm1 = (wid>>2)*64, wl1 = (wid&3)*16;
  const int wr2 = (wid>>2)*32, wn2 = (wid&3)*32;
  const int rk = tid>>2, ck = (tid&3)*16;
  const unsigned smQ = su32(Qs), smK = su32(Ks), smX = su32(Xs), smP = su32(Ps);
  const int laneA = (((lane&7) + ((lane>>3)&1)*8)*72 + ((lane>>4)&1)*8)*2;
  const int laneB = (((lane&7) + ((lane>>4)&1)*8)*72 + ((lane>>3)&1)*8)*2;

  {
    int r = tid>>1, sg = (tid&1)*32;
    const uint4* s = (const uint4*)&Qb[(size_t)(m0 + r)*64 + sg];
    uint4* d = (uint4*)&Qs[r*72 + sg];
    d[0]=s[0]; d[1]=s[1]; d[2]=s[2]; d[3]=s[3];
  }
  {
    float4 z = *(const float4*)&Z[(size_t)bh*1024 + tid*4];
    Zr[tid*4+0] = __frcp_rn(z.x);
    Zr[tid*4+1] = __frcp_rn(z.y);
    Zr[tid*4+2] = __frcp_rn(z.z);
    Zr[tid*4+3] = __frcp_rn(z.w);
  }
  __syncthreads();

  float O[2][4][4] = {};
  uint4 pk0, pk1, px0, px1;
  {
    const uint4* s = (const uint4*)&Kb[(size_t)rk*64 + ck];
    pk0 = s[0]; pk1 = s[1];
    const uint4* t = (const uint4*)&Xh[(size_t)rk*1024 + ck];
    px0 = t[0]; px1 = t[1];
  }

  for (int l0 = 0; l0 < 1024; l0 += 64) {
    __syncthreads();
    {
      uint4* d = (uint4*)&Ks[rk*72 + ck];
      d[0] = pk0; d[1] = pk1;
      unsigned pxw[8] = {px0.x, px0.y, px0.z, px0.w, px1.x, px1.y, px1.z, px1.w};
#pragma unroll
      for (int j = 0; j < 8; j++) {
        __half2 hv = *(__half2*)&pxw[j];
        float2 f = __half22float2(hv);
        f.x *= Zr[l0 + ck + 2*j];
        f.y *= Zr[l0 + ck + 2*j + 1];
        Xs2[rk*36 + (ck>>1) + j] = f2h2(f.x, f.y);
      }
    }
    __syncthreads();
    if (l0 < 960) {
      const uint4* s = (const uint4*)&Kb[(size_t)(l0 + 64 + rk)*64 + ck];
      pk0 = s[0]; pk1 = s[1];
      const uint4* t = (const uint4*)&Xh[(size_t)rk*1024 + l0 + 64 + ck];
      px0 = t[0]; px1 = t[1];
    }
    // GEMM1: S^T[m 128][l 64] = Q^T K
    float S[4][2][4] = {};
#pragma unroll
    for (int c = 0; c < 4; c++) {
      unsigned a[4][4], bb[2][2];
#pragma unroll
      for (int mt = 0; mt < 4; mt++)
        LDSM4(a[mt][0], a[mt][1], a[mt][2], a[mt][3],
              smQ + ((wm1 + mt*16)*72 + c*16)*2 + laneA);
      LDSM4(bb[0][0], bb[0][1], bb[1][0], bb[1][1],
            smK + (wl1*72 + c*16)*2 + laneB);
#pragma unroll
      for (int mt = 0; mt < 4; mt++)
#pragma unroll
        for (int nt = 0; nt < 2; nt++)
          mma16(S[mt][nt], a[mt][0],a[mt][1],a[mt][2],a[mt][3],
                bb[nt][0], bb[nt][1]);
    }
    // exp -> Ps[m][l]
#pragma unroll
    for (int mt = 0; mt < 4; mt++) {
      int m_ = wm1 + mt*16 + gi;
#pragma unroll
      for (int nt = 0; nt < 2; nt++) {
        int lu = wl1/2 + nt*4 + tj;
        Ps2[m_*36 + lu] =
            f2h2(__expf(S[mt][nt][0]*INV_TAU), __expf(S[mt][nt][1]*INV_TAU));
        Ps2[(m_+8)*36 + lu] =
            f2h2(__expf(S[mt][nt][2]*INV_TAU), __expf(S[mt][nt][3]*INV_TAU));
      }
    }
    __syncthreads();
    // GEMM2: O[d 64][m 128] += X'[d][l] @ P^T
#pragma unroll
    for (int c = 0; c < 4; c++) {
      unsigned a[2][4], bb[4][2];
#pragma unroll
      for (int mt = 0; mt < 2; mt++)
        LDSM4(a[mt][0], a[mt][1], a[mt][2], a[mt][3],
              smX + ((wr2 + mt*16)*72 + c*16)*2 + laneA);
      LDSM4(bb[0][0], bb[0][1], bb[1][0], bb[1][1],
            smP + (wn2*72 + c*16)*2 + laneB);
      LDSM4(bb[2][0], bb[2][1], bb[3][0], bb[3][1],
            smP + ((wn2 + 16)*72 + c*16)*2 + laneB);
#pragma unroll
      for (int mt = 0; mt < 2; mt++)
#pragma unroll
        for (int nt = 0; nt < 4; nt++)
          mma16(O[mt][nt], a[mt][0],a[mt][1],a[mt][2],a[mt][3],
                bb[nt][0], bb[nt][1]);
    }
  }
  // Epilogue
  __syncthreads();
  __half* Os = Qs;
#pragma unroll
  for (int mt = 0; mt < 2; mt++) {
    int d_ = wr2 + mt*16 + gi;
#pragma unroll
    for (int nt = 0; nt < 4; nt++) {
      int m_ = wn2 + nt*8 + 2*tj;
      Os[m_*72 + d_]       = __float2half(O[mt][nt][0]);
      Os[(m_+1)*72 + d_]   = __float2half(O[mt][nt][1]);
      Os[m_*72 + d_+8]     = __float2half(O[mt][nt][2]);
      Os[(m_+1)*72 + d_+8] = __float2half(O[mt][nt][3]);
    }
  }
  __syncthreads();
  {
    int m = tid>>1, sg = (tid&1)*32;
    const uint4* s = (const uint4*)&Os[m*72 + sg];
    uint4 v0 = s[0], v1 = s[1], v2 = s[2], v3 = s[3];
    __half* dst = &Ot[((size_t)b*1024 + m0 + m)*1024 + h*64 + sg];
    *(uint4*)dst        = v0;
    *(uint4*)(dst + 8)  = v1;
    *(uint4*)(dst + 16) = v2;
    *(uint4*)(dst + 24) = v3;
  }
}

// ---------------------------------------------------------------------------
extern "C" void kernel_launch(void* const* d_in, const int* in_sizes, int n_in,
                              void* d_out, int out_size) {
  (void)in_sizes; (void)n_in; (void)out_size;
  const float* x  = (const float*)d_in[0];
  const float* y  = (const float*)d_in[1];
  const float* Wk = (const float*)d_in[2];
  const float* bk = (const float*)d_in[3];
  const float* Wq = (const float*)d_in[4];
  const float* bq = (const float*)d_in[5];
  const float* Wp = (const float*)d_in[6];
  const float* bp = (const float*)d_in[7];
  float* out = (float*)d_out;

  __half *Xt, *Yt, *Otp, *X16, *Wh, *Ktp, *Qtp; float* Zp;
  cudaGetSymbolAddress((void**)&Xt,  g_Xt);
  cudaGetSymbolAddress((void**)&Yt,  g_Yt);
  cudaGetSymbolAddress((void**)&Otp, g_Ot);
  cudaGetSymbolAddress((void**)&X16, g_X16);
  cudaGetSymbolAddress((void**)&Wh,  g_Wh);
  cudaGetSymbolAddress((void**)&Ktp, g_Kt);
  cudaGetSymbolAddress((void**)&Qtp, g_Qt);
  cudaGetSymbolAddress((void**)&Zp,  g_Z);

  const int psmem = 2*20480;
  const int zsmem = 27648*2 + 1024;
  const int osmem = (9216+4608+4608+9216)*2 + 1024*4;
  cudaFuncSetAttribute(proj_h,  cudaFuncAttributeMaxDynamicSharedMemorySize, psmem);
  cudaFuncSetAttribute(zpass_h, cudaFuncAttributeMaxDynamicSharedMemorySize, zsmem);
  cudaFuncSetAttribute(opass_h, cudaFuncAttributeMaxDynamicSharedMemorySize, osmem);

  dim3 tg(16, 16, 8), pg(8, 8, 8);
  cvt16<<<1024, 256>>>(Wk, Wh);
  cvt16<<<1024, 256>>>(Wq, Wh + 1024*1024);
  cvt16<<<1024, 256>>>(Wp, Wh + 2ul*1024*1024);
  cvt16<<<8192, 256>>>(x, X16);
  prep_t<<<tg, 256>>>(x, Xt);
  prep_t<<<tg, 256>>>(y, Yt);
  proj_h<<<pg, 256, psmem>>>(Wh, Xt, bk, nullptr, Ktp, 0);
  proj_h<<<pg, 256, psmem>>>(Wh + 1024*1024, Yt, bq, nullptr, Qtp, 0);
  zpass_h<<<dim3(8, 128), 256, zsmem>>>(Ktp, Qtp, Zp);
  opass_h<<<dim3(8, 128), 256, osmem>>>(X16, Ktp, Qtp, Zp, Otp);
  proj_h<<<pg, 256, psmem>>>(Wh + 2ul*1024*1024, Otp, bp, out, nullptr, 1);
}

// round 14
// speedup vs baseline: 4.4215x; 1.1118x over previous
#include <cuda_runtime.h>
#include <cuda_fp16.h>

#define INV_TAU (1.0f/512.0f)

// Scratch (no cudaMalloc allowed)
__device__ __half g_Xt[8ul*1024*1024];     // x^T fp16 [b][l][s]
__device__ __half g_Yt[8ul*1024*1024];     // y^T fp16 [b][l][s]
__device__ __half g_Ot[8ul*1024*1024];     // O^T fp16 [b][m][s]
__device__ __half g_X16[8ul*1024*1024];    // x fp16 [b][s][l]
__device__ __half g_Xd[8ul*1024*1024];     // x/Z fp16 [b][s][l]
__device__ __half g_Wh[3ul*1024*1024];     // Wk,Wq,Wp fp16 row-major
__device__ __half g_Kt[128ul*1024*64];     // K^T fp16 [bh][l][d]
__device__ __half g_Qt[128ul*1024*64];     // Q^T fp16 [bh][m][d]
__device__ float  g_Z[128ul*1024];

__device__ __forceinline__ unsigned f2h2(float a, float b) {
  __half2 h = __floats2half2_rn(a, b);
  return *(unsigned*)&h;
}
__device__ __forceinline__ unsigned su32(const void* p) {
  unsigned a;
  asm("{ .reg .u64 t; cvta.to.shared.u64 t, %1; cvt.u32.u64 %0, t; }"
      : "=r"(a) : "l"(p));
  return a;
}
__device__ __forceinline__ void mma16(float* c, unsigned a0, unsigned a1,
                                      unsigned a2, unsigned a3,
                                      unsigned b0, unsigned b1) {
  asm("mma.sync.aligned.m16n8k16.row.col.f32.f16.f16.f32 "
      "{%0,%1,%2,%3}, {%4,%5,%6,%7}, {%8,%9}, {%0,%1,%2,%3};"
      : "+f"(c[0]), "+f"(c[1]), "+f"(c[2]), "+f"(c[3])
      : "r"(a0), "r"(a1), "r"(a2), "r"(a3), "r"(b0), "r"(b1));
}
#define LDSM4(r0, r1, r2, r3, addr) \
  asm volatile("ldmatrix.sync.aligned.m8n8.x4.shared.b16 {%0,%1,%2,%3}, [%4];" \
               : "=r"(r0), "=r"(r1), "=r"(r2), "=r"(r3) : "r"(addr))
__device__ __forceinline__ void cpa16(unsigned dst, const void* src) {
  asm volatile("cp.async.ca.shared.global [%0], [%1], 16;"
               :: "r"(dst), "l"(src));
}
#define CP_COMMIT() asm volatile("cp.async.commit_group;")
#define CP_WAIT1()  asm volatile("cp.async.wait_group 1;")
#define CP_WAIT0()  asm volatile("cp.async.wait_group 0;")

// ---------------------------------------------------------------------------
__global__ __launch_bounds__(256) void cvt16(
    const float* __restrict__ in, __half* __restrict__ out) {
  size_t i = ((size_t)blockIdx.x*256 + threadIdx.x)*4;
  float4 v = *(const float4*)&in[i];
  *(uint2*)&out[i] = make_uint2(f2h2(v.x, v.y), f2h2(v.z, v.w));
}

// ---------------------------------------------------------------------------
__global__ __launch_bounds__(256) void xdiv(
    const __half* __restrict__ X16, const float* __restrict__ Z,
    __half* __restrict__ Xd) {
  size_t i = ((size_t)blockIdx.x*256 + threadIdx.x)*4;
  int l = (int)(i & 1023), s = (int)((i>>10)&1023), b = (int)(i>>20);
  int bh = b*16 + (s>>6);
  float4 z = *(const float4*)&Z[(size_t)bh*1024 + l];
  uint2 v = *(const uint2*)&X16[i];
  float2 f0 = __half22float2(*(__half2*)&v.x);
  float2 f1 = __half22float2(*(__half2*)&v.y);
  *(uint2*)&Xd[i] = make_uint2(
      f2h2(f0.x*__frcp_rn(z.x), f0.y*__frcp_rn(z.y)),
      f2h2(f1.x*__frcp_rn(z.z), f1.y*__frcp_rn(z.w)));
}

// ---------------------------------------------------------------------------
__global__ __launch_bounds__(256, 2) void prep_t(
    const float* __restrict__ in, __half* __restrict__ out) {
  __shared__ float t[64][65];
  const int z = blockIdx.z;
  const int r0 = blockIdx.y * 64, c0 = blockIdx.x * 64;
  const int tid = threadIdx.x;
  const size_t base = (size_t)z * 1024 * 1024;
  const int tr = tid >> 4, tc4 = (tid & 15) * 4;
#pragma unroll
  for (int i = 0; i < 4; i++) {
    int row = tr + i * 16;
    float4 v = *(const float4*)&in[base + (size_t)(r0 + row) * 1024 + c0 + tc4];
    t[row][tc4+0] = v.x; t[row][tc4+1] = v.y;
    t[row][tc4+2] = v.z; t[row][tc4+3] = v.w;
  }
  __syncthreads();
#pragma unroll
  for (int i = 0; i < 4; i++) {
    int orow = tr + i * 16;
    uint2 u;
    u.x = f2h2(t[tc4+0][orow], t[tc4+1][orow]);
    u.y = f2h2(t[tc4+2][orow], t[tc4+3][orow]);
    *(uint2*)&out[base + (size_t)(c0 + orow) * 1024 + r0 + tc4] = u;
  }
}

// ---------------------------------------------------------------------------
// proj: C = W fp16 @ X + bias.  k-step 64, cp.async double buffer.
// mode 0 (grid z=16): which = z>>3 selects (W0,X0,b0,T0) or (W1,X1,b1,T1),
//   fp16 transposed per-head output.  mode 1 (grid z=8): set 0, fp32 out.
// smem halves: A0@0 A1@9216 B0@18432 B1@27648 (stride 72), total 36864.
// ---------------------------------------------------------------------------
__global__ __launch_bounds__(256, 2) void proj_h(
    const __half* __restrict__ W0, const __half* __restrict__ W1,
    const __half* __restrict__ X0, const __half* __restrict__ X1,
    const float* __restrict__ b0f, const float* __restrict__ b1f,
    __half* __restrict__ T0, __half* __restrict__ T1,
    float* __restrict__ Cout, int mode) {
  extern __shared__ __half psm[];
  const int z = blockIdx.z;
  const int which = (mode == 0) ? (z >> 3) : 0;
  const int b = z & 7;
  const __half* Wsel = which ? W1 : W0;
  const __half* Xsel = (which ? X1 : X0) + (size_t)b*1024*1024;
  const float* bias = which ? b1f : b0f;
  const int row0 = blockIdx.y*128, col0 = blockIdx.x*128;
  const int tid = threadIdx.x, wid = tid>>5, lane = tid&31;
  const int gi = lane>>2, tj = lane&3;
  const int wm = (wid>>2)*64, wn = (wid&3)*32;
  const unsigned smA = su32(psm);
  const int laneA = (((lane&7) + ((lane>>3)&1)*8)*72 + ((lane>>4)&1)*8)*2;
  const int laneB = (((lane&7) + ((lane>>4)&1)*8)*72 + ((lane>>3)&1)*8)*2;

  float acc[4][4][4] = {};

  // issue stage: 4 A-chunks + 4 B-chunks of 16B per thread
  auto issue = [&](int buf, int k0) {
#pragma unroll
    for (int i = 0; i < 4; i++) {
      int id = tid*4 + i;                 // 0..1023
      int row = id>>3, c8 = (id&7)*8;
      cpa16(smA + (buf*9216 + row*72 + c8)*2,
            &Wsel[(size_t)(row0 + row)*1024 + k0 + c8]);
      cpa16(smA + (18432 + buf*9216 + row*72 + c8)*2,
            &Xsel[(size_t)(col0 + row)*1024 + k0 + c8]);
    }
    CP_COMMIT();
  };
  issue(0, 0);
  issue(1, 64);

  for (int s = 0; s < 16; s++) {
    const int cur = s & 1;
    if (s < 15) CP_WAIT1(); else CP_WAIT0();
    __syncthreads();
#pragma unroll
    for (int c = 0; c < 4; c++) {
      unsigned a[4][4], bb[4][2];
#pragma unroll
      for (int mt = 0; mt < 4; mt++)
        LDSM4(a[mt][0], a[mt][1], a[mt][2], a[mt][3],
              smA + (cur*9216 + (wm + mt*16)*72 + c*16)*2 + laneA);
      LDSM4(bb[0][0], bb[0][1], bb[1][0], bb[1][1],
            smA + (18432 + cur*9216 + wn*72 + c*16)*2 + laneB);
      LDSM4(bb[2][0], bb[2][1], bb[3][0], bb[3][1],
            smA + (18432 + cur*9216 + (wn + 16)*72 + c*16)*2 + laneB);
#pragma unroll
      for (int mt = 0; mt < 4; mt++)
#pragma unroll
        for (int nt = 0; nt < 4; nt++)
          mma16(acc[mt][nt], a[mt][0],a[mt][1],a[mt][2],a[mt][3],
                bb[nt][0], bb[nt][1]);
    }
    __syncthreads();
    if (s < 14) issue(cur, (s + 2)*64);
  }

  if (mode == 1) {
    float* Cb = Cout + (size_t)b*1024*1024;
#pragma unroll
    for (int mt = 0; mt < 4; mt++) {
      int r0_ = row0 + wm + mt*16 + gi;
      float bv0 = bias[r0_], bv1 = bias[r0_+8];
#pragma unroll
      for (int nt = 0; nt < 4; nt++) {
        int cc = col0 + wn + nt*8 + 2*tj;
        *(float2*)&Cb[(size_t)r0_*1024 + cc] =
            make_float2(acc[mt][nt][0]+bv0, acc[mt][nt][1]+bv0);
        *(float2*)&Cb[(size_t)(r0_+8)*1024 + cc] =
            make_float2(acc[mt][nt][2]+bv1, acc[mt][nt][3]+bv1);
      }
    }
  } else {
    __half* Tout = which ? T1 : T0;
    __half* Cts = psm;   // 128*136 halves
#pragma unroll
    for (int mt = 0; mt < 4; mt++) {
      int r_ = wm + mt*16 + gi;
      float bv0 = bias[row0 + r_], bv1 = bias[row0 + r_ + 8];
#pragma unroll
      for (int nt = 0; nt < 4; nt++) {
        int c_ = wn + nt*8 + 2*tj;
        Cts[c_*136 + r_]       = __float2half(acc[mt][nt][0] + bv0);
        Cts[(c_+1)*136 + r_]   = __float2half(acc[mt][nt][1] + bv0);
        Cts[c_*136 + r_+8]     = __float2half(acc[mt][nt][2] + bv1);
        Cts[(c_+1)*136 + r_+8] = __float2half(acc[mt][nt][3] + bv1);
      }
    }
    __syncthreads();
    int l = tid>>1, part = tid&1;
    size_t obase = ((size_t)(b*16 + (row0>>6) + part)*1024 + col0 + l)*64;
#pragma unroll
    for (int j = 0; j < 8; j++)
      *(uint4*)&Tout[obase + j*8] = *(const uint4*)&Cts[l*136 + part*64 + j*8];
  }
}

// ---------------------------------------------------------------------------
// zpass (unchanged from R13): Z[l] = sum_m exp(S[l,m]/tau), S^T = Q^T K.
// ---------------------------------------------------------------------------
__global__ __launch_bounds__(256, 2) void zpass_h(
    const __half* __restrict__ Kt, const __half* __restrict__ Qt,
    float* __restrict__ Z) {
  extern __shared__ __half zsm[];
  __half* Ks = zsm;
  __half* Qs = zsm + 9216;
  float* Zp = (float*)(zsm + 27648);
  const int bh = blockIdx.y, l0 = blockIdx.x*128;
  const __half* Kb = Kt + (size_t)bh*65536;
  const __half* Qb = Qt + (size_t)bh*65536;
  const int tid = threadIdx.x, wid = tid>>5, lane = tid&31;
  const int gi = lane>>2, tj = lane&3;
  const int wm_ = (wid>>2)*64, wl_ = (wid&3)*32;
  const int r = tid>>1, sg = (tid&1)*32;
  const unsigned smK = su32(Ks), smQ = su32(Qs);
  const int laneA = (((lane&7) + ((lane>>3)&1)*8)*72 + ((lane>>4)&1)*8)*2;
  const int laneB = (((lane&7) + ((lane>>4)&1)*8)*72 + ((lane>>3)&1)*8)*2;

  {
    const uint4* s = (const uint4*)&Kb[(size_t)(l0 + r)*64 + sg];
    uint4* d = (uint4*)&Ks[r*72 + sg];
    d[0]=s[0]; d[1]=s[1]; d[2]=s[2]; d[3]=s[3];
  }
  uint4 pq[4];
  {
    const uint4* s = (const uint4*)&Qb[(size_t)r*64 + sg];
    pq[0]=s[0]; pq[1]=s[1]; pq[2]=s[2]; pq[3]=s[3];
    uint4* d = (uint4*)&Qs[r*72 + sg];
    d[0]=pq[0]; d[1]=pq[1]; d[2]=pq[2]; d[3]=pq[3];
  }
  __syncthreads();

  float rs[4][2] = {};
  for (int m0 = 0; m0 < 1024; m0 += 128) {
    const int cur = (m0 >> 7) & 1, nxt = cur ^ 1;
    if (m0 < 896) {
      const uint4* s = (const uint4*)&Qb[(size_t)(m0 + 128 + r)*64 + sg];
      pq[0]=s[0]; pq[1]=s[1]; pq[2]=s[2]; pq[3]=s[3];
    }
    float S[4][4][4] = {};
#pragma unroll
    for (int c = 0; c < 4; c++) {
      unsigned a[4][4], bb[4][2];
#pragma unroll
      for (int mt = 0; mt < 4; mt++)
        LDSM4(a[mt][0], a[mt][1], a[mt][2], a[mt][3],
              smQ + cur*18432 + ((wm_ + mt*16)*72 + c*16)*2 + laneA);
      LDSM4(bb[0][0], bb[0][1], bb[1][0], bb[1][1],
            smK + (wl_*72 + c*16)*2 + laneB);
      LDSM4(bb[2][0], bb[2][1], bb[3][0], bb[3][1],
            smK + ((wl_ + 16)*72 + c*16)*2 + laneB);
#pragma unroll
      for (int mt = 0; mt < 4; mt++)
#pragma unroll
        for (int nt = 0; nt < 4; nt++)
          mma16(S[mt][nt], a[mt][0],a[mt][1],a[mt][2],a[mt][3],
                bb[nt][0], bb[nt][1]);
    }
#pragma unroll
    for (int mt = 0; mt < 4; mt++)
#pragma unroll
      for (int nt = 0; nt < 4; nt++) {
        rs[nt][0] += __expf(S[mt][nt][0]*INV_TAU) + __expf(S[mt][nt][2]*INV_TAU);
        rs[nt][1] += __expf(S[mt][nt][1]*INV_TAU) + __expf(S[mt][nt][3]*INV_TAU);
      }
    if (m0 < 896) {
      uint4* d = (uint4*)&Qs[nxt*9216 + r*72 + sg];
      d[0]=pq[0]; d[1]=pq[1]; d[2]=pq[2]; d[3]=pq[3];
    }
    __syncthreads();
  }
#pragma unroll
  for (int nt = 0; nt < 4; nt++)
#pragma unroll
    for (int j = 0; j < 2; j++) {
      float v = rs[nt][j];
      v += __shfl_xor_sync(0xffffffffu, v, 4);
      v += __shfl_xor_sync(0xffffffffu, v, 8);
      v += __shfl_xor_sync(0xffffffffu, v, 16);
      rs[nt][j] = v;
    }
  if (gi == 0) {
#pragma unroll
    for (int nt = 0; nt < 4; nt++)
#pragma unroll
      for (int j = 0; j < 2; j++)
        Zp[(wid>>2)*128 + wl_ + nt*8 + 2*tj + j] = rs[nt][j];
  }
  __syncthreads();
  if (tid < 128)
    Z[(size_t)bh*1024 + l0 + tid] = Zp[tid] + Zp[128 + tid];
}

// ---------------------------------------------------------------------------
// opass: O[d,m] = sum_l xd[d,l] * exp(S[l,m]/tau)  (xd pre-scaled by 1/Z).
// cp.async double-buffered K and Xd; l-chunk 64; ldmatrix fragments.
// smem halves: Qs@0 (9216), K0@9216 K1@13824 (4608 ea), X0@18432 X1@23040,
//              Ps@27648 (9216).  Total 36864.
// ---------------------------------------------------------------------------
__global__ __launch_bounds__(256, 2) void opass_h(
    const __half* __restrict__ Xd, const __half* __restrict__ Kt,
    const __half* __restrict__ Qt, __half* __restrict__ Ot) {
  extern __shared__ __half osm[];
  __half* Qs = osm;
  unsigned* Ps2 = (unsigned*)(osm + 27648);
  const int bh = blockIdx.y, m0 = blockIdx.x*128;
  const int b = bh>>4, h = bh&15;
  const __half* Kb = Kt + (size_t)bh*65536;
  const __half* Qb = Qt + (size_t)bh*65536;
  const __half* Xg = Xd + ((size_t)b*1024 + h*64)*1024;
  const int tid = threadIdx.x, wid = tid>>5, lane = tid&31;
  const int gi = lane>>2, tj = lane&3;
  const int wm1 = (wid>>2)*64, wl1 = (wid&3)*16;
  const int wr2 = (wid>>2)*32, wn2 = (wid&3)*32;
  const unsigned smO = su32(osm);
  const int laneA = (((lane&7) + ((lane>>3)&1)*8)*72 + ((lane>>4)&1)*8)*2;
  const int laneB = (((lane&7) + ((lane>>4)&1)*8)*72 + ((lane>>3)&1)*8)*2;

  {
    int r = tid>>1, sg = (tid&1)*32;
    const uint4* s = (const uint4*)&Qb[(size_t)(m0 + r)*64 + sg];
    uint4* d = (uint4*)&Qs[r*72 + sg];
    d[0]=s[0]; d[1]=s[1]; d[2]=s[2]; d[3]=s[3];
  }

  auto issue = [&](int buf, int l0) {
#pragma unroll
    for (int i = 0; i < 2; i++) {
      int id = tid*2 + i;                 // 0..511
      int row = id>>3, c8 = (id&7)*8;
      cpa16(smO + (9216 + buf*4608 + row*72 + c8)*2,
            &Kb[(size_t)(l0 + row)*64 + c8]);
      cpa16(smO + (18432 + buf*4608 + row*72 + c8)*2,
            &Xg[(size_t)row*1024 + l0 + c8]);
    }
    CP_COMMIT();
  };
  issue(0, 0);
  issue(1, 64);

  float O[2][4][4] = {};
  for (int s = 0; s < 16; s++) {
    const int cur = s & 1;
    if (s < 15) CP_WAIT1(); else CP_WAIT0();
    __syncthreads();
    // GEMM1: S^T[m 128][l 64] = Q^T K
    float S[4][2][4] = {};
#pragma unroll
    for (int c = 0; c < 4; c++) {
      unsigned a[4][4], bb[2][2];
#pragma unroll
      for (int mt = 0; mt < 4; mt++)
        LDSM4(a[mt][0], a[mt][1], a[mt][2], a[mt][3],
              smO + ((wm1 + mt*16)*72 + c*16)*2 + laneA);
      LDSM4(bb[0][0], bb[0][1], bb[1][0], bb[1][1],
            smO + (9216 + cur*4608 + wl1*72 + c*16)*2 + laneB);
#pragma unroll
      for (int mt = 0; mt < 4; mt++)
#pragma unroll
        for (int nt = 0; nt < 2; nt++)
          mma16(S[mt][nt], a[mt][0],a[mt][1],a[mt][2],a[mt][3],
                bb[nt][0], bb[nt][1]);
    }
    // exp -> Ps[m][l]
#pragma unroll
    for (int mt = 0; mt < 4; mt++) {
      int m_ = wm1 + mt*16 + gi;
#pragma unroll
      for (int nt = 0; nt < 2; nt++) {
        int lu = wl1/2 + nt*4 + tj;
        Ps2[m_*36 + lu] =
            f2h2(__expf(S[mt][nt][0]*INV_TAU), __expf(S[mt][nt][1]*INV_TAU));
        Ps2[(m_+8)*36 + lu] =
            f2h2(__expf(S[mt][nt][2]*INV_TAU), __expf(S[mt][nt][3]*INV_TAU));
      }
    }
    __syncthreads();
    // GEMM2: O[d 64][m 128] += Xd[d][l] @ P^T
#pragma unroll
    for (int c = 0; c < 4; c++) {
      unsigned a[2][4], bb[4][2];
#pragma unroll
      for (int mt = 0; mt < 2; mt++)
        LDSM4(a[mt][0], a[mt][1], a[mt][2], a[mt][3],
              smO + (18432 + cur*4608 + (wr2 + mt*16)*72 + c*16)*2 + laneA);
      LDSM4(bb[0][0], bb[0][1], bb[1][0], bb[1][1],
            smO + (27648 + wn2*72 + c*16)*2 + laneB);
      LDSM4(bb[2][0], bb[2][1], bb[3][0], bb[3][1],
            smO + (27648 + (wn2 + 16)*72 + c*16)*2 + laneB);
#pragma unroll
      for (int mt = 0; mt < 2; mt++)
#pragma unroll
        for (int nt = 0; nt < 4; nt++)
          mma16(O[mt][nt], a[mt][0],a[mt][1],a[mt][2],a[mt][3],
                bb[nt][0], bb[nt][1]);
    }
    __syncthreads();
    if (s < 14) issue(cur, (s + 2)*64);
  }
  // Epilogue: stage Os[m 128][d 64] over Qs, coalesced write
  __half* Os = Qs;
#pragma unroll
  for (int mt = 0; mt < 2; mt++) {
    int d_ = wr2 + mt*16 + gi;
#pragma unroll
    for (int nt = 0; nt < 4; nt++) {
      int m_ = wn2 + nt*8 + 2*tj;
      Os[m_*72 + d_]       = __float2half(O[mt][nt][0]);
      Os[(m_+1)*72 + d_]   = __float2half(O[mt][nt][1]);
      Os[m_*72 + d_+8]     = __float2half(O[mt][nt][2]);
      Os[(m_+1)*72 + d_+8] = __float2half(O[mt][nt][3]);
    }
  }
  __syncthreads();
  {
    int m = tid>>1, sg = (tid&1)*32;
    const uint4* s = (const uint4*)&Os[m*72 + sg];
    uint4 v0 = s[0], v1 = s[1], v2 = s[2], v3 = s[3];
    __half* dst = &Ot[((size_t)b*1024 + m0 + m)*1024 + h*64 + sg];
    *(uint4*)dst        = v0;
    *(uint4*)(dst + 8)  = v1;
    *(uint4*)(dst + 16) = v2;
    *(uint4*)(dst + 24) = v3;
  }
}

// ---------------------------------------------------------------------------
extern "C" void kernel_launch(void* const* d_in, const int* in_sizes, int n_in,
                              void* d_out, int out_size) {
  (void)in_sizes; (void)n_in; (void)out_size;
  const float* x  = (const float*)d_in[0];
  const float* y  = (const float*)d_in[1];
  const float* Wk = (const float*)d_in[2];
  const float* bk = (const float*)d_in[3];
  const float* Wq = (const float*)d_in[4];
  const float* bq = (const float*)d_in[5];
  const float* Wp = (const float*)d_in[6];
  const float* bp = (const float*)d_in[7];
  float* out = (float*)d_out;

  __half *Xt, *Yt, *Otp, *X16, *Xdp, *Wh, *Ktp, *Qtp; float* Zp;
  cudaGetSymbolAddress((void**)&Xt,  g_Xt);
  cudaGetSymbolAddress((void**)&Yt,  g_Yt);
  cudaGetSymbolAddress((void**)&Otp, g_Ot);
  cudaGetSymbolAddress((void**)&X16, g_X16);
  cudaGetSymbolAddress((void**)&Xdp, g_Xd);
  cudaGetSymbolAddress((void**)&Wh,  g_Wh);
  cudaGetSymbolAddress((void**)&Ktp, g_Kt);
  cudaGetSymbolAddress((void**)&Qtp, g_Qt);
  cudaGetSymbolAddress((void**)&Zp,  g_Z);

  const int psmem = 36864*2;            // 73,728 B
  const int zsmem = 27648*2 + 1024;     // 56,320 B
  const int osmem = 36864*2;            // 73,728 B
  cudaFuncSetAttribute(proj_h,  cudaFuncAttributeMaxDynamicSharedMemorySize, psmem);
  cudaFuncSetAttribute(zpass_h, cudaFuncAttributeMaxDynamicSharedMemorySize, zsmem);
  cudaFuncSetAttribute(opass_h, cudaFuncAttributeMaxDynamicSharedMemorySize, osmem);

  dim3 tg(16, 16, 8);
  cvt16<<<1024, 256>>>(Wk, Wh);
  cvt16<<<1024, 256>>>(Wq, Wh + 1024*1024);
  cvt16<<<1024, 256>>>(Wp, Wh + 2ul*1024*1024);
  cvt16<<<8192, 256>>>(x, X16);
  prep_t<<<tg, 256>>>(x, Xt);
  prep_t<<<tg, 256>>>(y, Yt);
  // merged K + Q projections (z = 16: low 8 = batch, high bit = which)
  proj_h<<<dim3(8, 8, 16), 256, psmem>>>(Wh, Wh + 1024*1024, Xt, Yt,
                                         bk, bq, Ktp, Qtp, nullptr, 0);
  zpass_h<<<dim3(8, 128), 256, zsmem>>>(Ktp, Qtp, Zp);
  xdiv<<<8192, 256>>>(X16, Zp, Xdp);
  opass_h<<<dim3(8, 128), 256, osmem>>>(Xdp, Ktp, Qtp, Otp);
  // final projection (fp32 out)
  proj_h<<<dim3(8, 8, 8), 256, psmem>>>(Wh + 2ul*1024*1024, nullptr, Otp, nullptr,
                                        bp, nullptr, nullptr, nullptr, out, 1);
}